// round 14
// baseline (speedup 1.0000x reference)
#include <cuda_runtime.h>
#include <cmath>

// ---------------------------------------------------------------------------
// CTLNN persistent kernel, round 14: EIGHT staggered row-streams.
// 128 CTAs; each owns 4 H-columns. Each CTA splits into 8 streams of 64
// threads (8 batch rows each), cascaded one phase apart; each stream has its
// own stage buffers, distributed grid-barrier set, and bar.sync scope.
// Per stream: thread (r:8, ks:8) computes all 4 CTA columns over 8 granules.
// Epilogues distributed over the 64 threads; per-row recurrence state in
// SMEM. tau folded through the mapper (3 phases/step); LayerNorm folded into
// phase A; cp.async double-buffered staging; FFMA2 inner loops.
// ---------------------------------------------------------------------------

namespace {
constexpr int Tt   = 1024;
constexpr int DIN  = 256;
constexpr int Hh   = 512;
constexpr int NCTA = 128;
constexpr int NTHR = 512;
constexpr int NSTR = 8;             // row-streams per CTA
constexpr int NBAR = 16;
constexpr int BARSTRIDE = 32;
constexpr float DTc  = 0.01f;
constexpr float EPSc = 1e-5f;

// SMEM float offsets
constexpr int OFF_WMX   = 0;        // 8 x 256 (x-rows: 4 gate + 4 core cols)
constexpr int OFF_WMV   = 2048;     // 8 x 512 (h-rows, gamma-folded)
constexpr int OFF_WFX   = 6144;     // 4 x 256 tau x-fold
constexpr int OFF_WFV   = 7168;     // 4 x 512 tau v-fold (gamma-folded)
constexpr int OFF_WF1   = 9216;     // 4 x 512
constexpr int OFF_WF2   = 11264;    // 4 x 512
constexpr int OFF_STAGE = 13312;    // 8 streams x 2 buffers x 512 float4
constexpr int OFF_RED   = 46080;    // 8 streams x 64 x 3 float4 = 6144 floats
constexpr int OFF_B     = 52224;    // 64 consts
constexpr int OFF_ST    = 52288;    // 8 streams x 128 state floats
constexpr int SMEM_FLOATS = 53312;  // ~213.2 KB
// OFF_B: 0 bmg[4] 4 bmc[4] 8 tauC0[4] 12 bf1[4] 16 bf2[4] 20 gam[4] 24 bet[4]
//        28 Bsum[8] (g,core) 36 Gsum[8] 44 BsumT[4] 48 GsumT[4]
// per-stream state (128): 0 rstd[8] 8 mr[8] 16 dtT[32] 48 h[32] 80 v[32]
}

// Cross-CTA state
__device__ unsigned g_barArr[NSTR][NBAR * BARSTRIDE];   // per-stream counters
__device__ float g_rs[128], g_rq[128];                  // [par][globalRow]
__device__ float g_v[64 * Hh];
__device__ float g_z[64 * Hh];
__device__ float g_a1[64 * Hh];

__global__ void ctlnn_reset() {
    int i = blockIdx.x * blockDim.x + threadIdx.x;
    if (i < NSTR * NBAR * BARSTRIDE) (&g_barArr[0][0])[i] = 0u;
    if (i < 128) { g_rs[i] = 0.f; g_rq[i] = 0.f; }
    for (int k = i; k < 64 * Hh; k += gridDim.x * blockDim.x) g_v[k] = 0.f;
}

// ---- helpers --------------------------------------------------------------
__device__ __forceinline__ void cp16(float4* dst, const void* src) {
    unsigned s = (unsigned)__cvta_generic_to_shared(dst);
    asm volatile("cp.async.cg.shared.global [%0], [%1], 16;" :: "r"(s), "l"(src));
}
__device__ __forceinline__ void cp_commit() {
    asm volatile("cp.async.commit_group;" ::: "memory");
}
template <int N>
__device__ __forceinline__ void cp_wait() {
    asm volatile("cp.async.wait_group %0;" :: "n"(N) : "memory");
}
__device__ __forceinline__ void fma2(unsigned long long& d,
                                     unsigned long long a, unsigned long long b) {
    asm volatile("fma.rn.f32x2 %0, %1, %2, %3;" : "=l"(d) : "l"(a), "l"(b), "l"(d));
}
__device__ __forceinline__ unsigned long long mul2(unsigned long long a,
                                                   unsigned long long b) {
    unsigned long long d;
    asm("mul.rn.f32x2 %0, %1, %2;" : "=l"(d) : "l"(a), "l"(b));
    return d;
}
__device__ __forceinline__ float hsum(unsigned long long u) {
    float lo, hi;
    asm("mov.b64 {%0,%1}, %2;" : "=f"(lo), "=f"(hi) : "l"(u));
    return lo + hi;
}
// per-stream sync (named barrier, 64 threads)
__device__ __forceinline__ void sg_sync(int sid) {
    asm volatile("bar.sync %0, 64;" :: "r"(1 + sid) : "memory");
}

// Distributed per-stream grid barrier.
__device__ __forceinline__ void bar_arrive(int s, int wtid) {
    __threadfence();
    sg_sync(s);
    if (wtid == 0)
        atomicAdd(&g_barArr[s][(blockIdx.x & (NBAR - 1)) * BARSTRIDE], 1u);
}
__device__ __forceinline__ void bar_wait(int s, unsigned target8, int wtid) {
    if (wtid < NBAR) {
        unsigned v;
        do {
            asm volatile("ld.global.acquire.gpu.u32 %0, [%1];"
                         : "=r"(v) : "l"(&g_barArr[s][wtid * BARSTRIDE]));
        } while (v < target8);
    }
    sg_sync(s);
}

// Stage one 8-row x 64-granule(16B) chunk: 64 threads, 8 cp16 each.
__device__ __forceinline__ void stage8(float4* __restrict__ dst,
                                       const char* __restrict__ gbase,
                                       size_t rstrideB, int kk) {
#pragma unroll
    for (int rs = 0; rs < 8; ++rs) {
        cp16(dst + rs * 64 + (kk ^ rs),
             gbase + (size_t)rs * rstrideB + kk * 16);
    }
    cp_commit();
}

// 12-output chunk dot: 4 gate + 4 core + 4 tau. ws = weight granule stride.
template <bool SCALE>
__device__ __forceinline__ void dot12(const ulonglong2* __restrict__ sp, int sw,
                                      int ks, int goff,
                                      const ulonglong2* __restrict__ wg,
                                      const ulonglong2* __restrict__ wc,
                                      const ulonglong2* __restrict__ wt,
                                      int ws, unsigned long long sc,
                                      unsigned long long acc[12]) {
#pragma unroll
    for (int j = 0; j < 8; ++j) {
        int l = j * 8 + ks;
        ulonglong2 a = sp[l ^ sw];
        if (SCALE) { a.x = mul2(a.x, sc); a.y = mul2(a.y, sc); }
        int wi = goff + l;
#pragma unroll
        for (int cc = 0; cc < 4; ++cc) {
            ulonglong2 g = wg[cc * ws + wi];
            fma2(acc[cc], a.x, g.x); fma2(acc[cc], a.y, g.y);
            ulonglong2 c = wc[cc * ws + wi];
            fma2(acc[4 + cc], a.x, c.x); fma2(acc[4 + cc], a.y, c.y);
            ulonglong2 t2 = wt[cc * ws + wi];
            fma2(acc[8 + cc], a.x, t2.x); fma2(acc[8 + cc], a.y, t2.y);
        }
    }
}

// Generic 4-col dot (phases C/D), weight col stride 128 granules.
__device__ __forceinline__ void dot4(const ulonglong2* __restrict__ sp, int sw,
                                     int ks, int goff,
                                     const ulonglong2* __restrict__ w,
                                     unsigned long long acc[4][2]) {
#pragma unroll
    for (int j = 0; j < 8; ++j) {
        int l = j * 8 + ks;
        ulonglong2 a = sp[l ^ sw];
        int wi = goff + l;
#pragma unroll
        for (int cc = 0; cc < 4; ++cc) {
            ulonglong2 ww = w[cc * 128 + wi];
            fma2(acc[cc][0], a.x, ww.x);
            fma2(acc[cc][1], a.y, ww.y);
        }
    }
}

__global__ void __launch_bounds__(NTHR, 1)
ctlnn_main(const float* __restrict__ x,
           const float* __restrict__ Wm,  const float* __restrict__ bm,
           const float* __restrict__ Wf1, const float* __restrict__ bf1,
           const float* __restrict__ Wf2, const float* __restrict__ bf2,
           const float* __restrict__ Wt,  const float* __restrict__ bt,
           const float* __restrict__ gamma, const float* __restrict__ beta,
           float* __restrict__ out) {
    extern __shared__ __align__(16) float sm[];
    const int tid = threadIdx.x;
    const int bid = blockIdx.x;
    const int cbase = bid * 4;

    // ---- one-time weight slice load (whole CTA) ----
    for (int idx = tid; idx < 8 * 256; idx += NTHR) {    // Wm x-rows
        int c = idx >> 8, k = idx & 255;
        int srccol = (c < 4) ? (cbase + c) : (512 + cbase + (c - 4));
        sm[OFF_WMX + idx] = Wm[k * 1024 + srccol];
    }
    for (int idx = tid; idx < 8 * 512; idx += NTHR) {    // Wm h-rows * gamma
        int c = idx >> 9, k = idx & 511;
        int srccol = (c < 4) ? (cbase + c) : (512 + cbase + (c - 4));
        sm[OFF_WMV + idx] = Wm[(256 + k) * 1024 + srccol] * gamma[k];
    }
    for (int idx = tid; idx < 4 * 512; idx += NTHR) {
        int c = idx >> 9, k = idx & 511;
        int col = cbase + c;
        sm[OFF_WF1 + idx] = Wf1[k * 512 + col];
        sm[OFF_WF2 + idx] = Wf2[k * 512 + col];
    }
    for (int idx = tid; idx < NSTR * 128; idx += NTHR)   // zero state blocks
        sm[OFF_ST + idx] = 0.f;
    if (tid < 4) {
        int col = cbase + tid;
        sm[OFF_B +  0 + tid] = bm[col];
        sm[OFF_B +  4 + tid] = bm[512 + col];
        sm[OFF_B + 12 + tid] = bf1[col];
        sm[OFF_B + 16 + tid] = bf2[col];
        sm[OFF_B + 20 + tid] = gamma[col];
        sm[OFF_B + 24 + tid] = beta[col];
    }
    {   // Bsum/Gsum for the 8 A-columns (gate 0..3, core 4..7)
        int w = tid >> 5, lane = tid & 31;
        if (w < 8) {
            int srccol = (w < 4) ? (cbase + w) : (512 + cbase + (w - 4));
            float sb = 0.f, sg = 0.f;
            for (int k = lane; k < 512; k += 32) {
                float wv = Wm[(256 + k) * 1024 + srccol];
                sb += beta[k] * wv;
                sg += gamma[k] * wv;
            }
#pragma unroll
            for (int o = 16; o; o >>= 1) {
                sb += __shfl_xor_sync(~0u, sb, o);
                sg += __shfl_xor_sync(~0u, sg, o);
            }
            if (lane == 0) { sm[OFF_B + 28 + w] = sb; sm[OFF_B + 36 + w] = sg; }
        }
    }
    __syncthreads();
    // ---- tau fold: WfX = WmX_core@Wt, WfV = WmV_core@Wt (gamma-folded) ----
    {
        float* WtS = sm + OFF_STAGE;            // 4 x 512 [c][j]
        float* Tm  = sm + OFF_STAGE + 2048;     // 24 x 512 tile
        for (int idx = tid; idx < 4 * 512; idx += NTHR) {
            int c = idx >> 9, j = idx & 511;
            WtS[idx] = Wt[j * 512 + cbase + c];
        }
        __syncthreads();
        for (int tile = 0; tile < 32; ++tile) {
            int k0 = tile * 24;
            for (int idx = tid; idx < 24 * 128; idx += NTHR) {
                int row = idx >> 7, jj = idx & 127;
                reinterpret_cast<float4*>(Tm)[row * 128 + jj] =
                    __ldg(reinterpret_cast<const float4*>(
                        Wm + (size_t)(k0 + row) * 1024 + 512) + jj);
            }
            __syncthreads();
            int row = tid >> 2, c = tid & 3;
            if (row < 24) {
                const float4* tm = reinterpret_cast<const float4*>(Tm) + row * 128;
                const float4* wt4 = reinterpret_cast<const float4*>(WtS) + c * 128;
                float s = 0.f;
                for (int jj = 0; jj < 128; ++jj) {
                    float4 a = tm[jj], b = wt4[jj];
                    s += a.x * b.x + a.y * b.y + a.z * b.z + a.w * b.w;
                }
                int k = k0 + row;
                if (k < 256) sm[OFF_WFX + c * 256 + k] = s;
                else         sm[OFF_WFV + c * 512 + (k - 256)] = s;   // raw
            }
            __syncthreads();
        }
        int w = tid >> 5, lane = tid & 31;
        if (w >= 8 && w < 12) {             // BsumT/GsumT for c = w-8
            int c = w - 8;
            float sb = 0.f, sg = 0.f;
            for (int k = lane; k < 512; k += 32) {
                float raw = sm[OFF_WFV + c * 512 + k];
                sb += beta[k] * raw;
                sg += gamma[k] * raw;
            }
#pragma unroll
            for (int o = 16; o; o >>= 1) {
                sb += __shfl_xor_sync(~0u, sb, o);
                sg += __shfl_xor_sync(~0u, sg, o);
            }
            if (lane == 0) { sm[OFF_B + 44 + c] = sb; sm[OFF_B + 48 + c] = sg; }
        } else if (w >= 12) {               // tau const C0 for c = w-12
            int c = w - 12;
            float s = 0.f;
            for (int j = lane; j < 512; j += 32)
                s += bm[512 + j] * WtS[c * 512 + j];
#pragma unroll
            for (int o = 16; o; o >>= 1)
                s += __shfl_xor_sync(~0u, s, o);
            if (lane == 0) sm[OFF_B + 8 + c] = s + bt[cbase + c];
        }
        __syncthreads();
        for (int idx = tid; idx < 4 * 512; idx += NTHR)   // gamma-fold WFV
            sm[OFF_WFV + idx] *= gamma[idx & 511];
        __syncthreads();
    }

    // ---------------- per-stream state ----------------
    const int sid  = tid >> 6;          // stream 0..7
    const int wtid = tid & 63;
    const int r    = wtid & 7;          // local row
    const int ks   = wtid >> 3;         // K-slot (0..7)
    const int sw   = r;                 // swizzle key
    const int kk   = wtid;              // staging granule (0..63)
    const int gR   = sid * 8 + r;       // global batch row
    const int ec   = ks;                // epilogue item
    const int ecol = ec & 3;            // epilogue column

    float4* bufA = reinterpret_cast<float4*>(sm + OFF_STAGE) + sid * 1024;
    float4* bufB = bufA + 512;
    float4* red4 = reinterpret_cast<float4*>(sm + OFF_RED) + sid * 192;
    float* st      = sm + OFF_ST + sid * 128;
    float* st_rstd = st;          // 8
    float* st_mr   = st + 8;      // 8
    float* st_dtT  = st + 16;     // 32
    float* st_h    = st + 48;     // 32
    float* st_v    = st + 80;     // 32

    const ulonglong2* WMXg = reinterpret_cast<const ulonglong2*>(sm + OFF_WMX);
    const ulonglong2* WMXc = WMXg + 4 * 64;
    const ulonglong2* WFXu = reinterpret_cast<const ulonglong2*>(sm + OFF_WFX);
    const ulonglong2* WMVg = reinterpret_cast<const ulonglong2*>(sm + OFF_WMV);
    const ulonglong2* WMVc = WMVg + 4 * 128;
    const ulonglong2* WFVu = reinterpret_cast<const ulonglong2*>(sm + OFF_WFV);
    const ulonglong2* WF1u = reinterpret_cast<const ulonglong2*>(sm + OFF_WF1);
    const ulonglong2* WF2u = reinterpret_cast<const ulonglong2*>(sm + OFF_WF2);

    const char* xbase = (const char*)(x + (size_t)sid * 8 * Tt * DIN);
    const char* vbase = (const char*)(g_v  + (size_t)sid * 8 * Hh);
    const char* zbase = (const char*)(g_z  + (size_t)sid * 8 * Hh);
    const char* abase = (const char*)(g_a1 + (size_t)sid * 8 * Hh);

    unsigned bar_t = 0;

    // prefetch x(t=0) into bufA
    stage8(bufA, xbase, (size_t)Tt * DIN * 4, kk);

    // ---- cascade start: stream s waits for stream s-1's phase A of t=0 ----
    if (sid > 0) {
        if (wtid < NBAR) {
            unsigned v;
            do {
                asm volatile("ld.global.acquire.gpu.u32 %0, [%1];"
                             : "=r"(v) : "l"(&g_barArr[sid - 1][wtid * BARSTRIDE]));
            } while (v < 8);
        }
        sg_sync(sid);
    }

    for (int t = 0; t < Tt; ++t) {
        const int par = t & 1;

        // ============ PHASE A (12 outputs; LN + tau folded) ================
        unsigned long long acc[12] = {};
        cp_wait<0>(); sg_sync(sid);                        // x(t) ready (bufA)
        dot12<false>(reinterpret_cast<const ulonglong2*>(bufA) + r * 64, sw,
                     ks, 0, WMXg, WMXc, WFXu, 64, 0ull, acc);
        bar_wait(sid, bar_t, wtid);                        // hidden by x-dot
        stage8(bufB, vbase, Hh * 4, kk);                   // v0 -> B
        stage8(bufA, vbase + 1024, Hh * 4, kk);            // v1 -> A
        // finalize step t-1 (distributed: 32 threads (r, ecol))
        if (t > 0 && ec < 4) {
            int pp = (t - 1) & 1;
            float s = __ldcg(&g_rs[pp * 64 + gR]);
            float q = __ldcg(&g_rq[pp * 64 + gR]);
            float muv = s * (1.f / 512.f);
            float var = q * (1.f / 512.f) - muv * muv;
            float rstdv = rsqrtf(var + EPSc);
            float hn = (st_v[r * 4 + ecol] - muv) * rstdv
                       * sm[OFF_B + 20 + ecol] + sm[OFF_B + 24 + ecol];
            out[((size_t)gR * Tt + (t - 1)) * Hh + cbase + ecol] = hn;
            st_h[r * 4 + ecol] = hn;
            if (ecol == 0) { st_rstd[r] = rstdv; st_mr[r] = muv * rstdv; }
        }
        cp_wait<1>(); sg_sync(sid);                        // v0 ready, rstd vis
        unsigned long long rstd2;
        {
            float rv = st_rstd[r];
            asm("mov.b64 %0, {%1, %1};" : "=l"(rstd2) : "f"(rv));
        }
        dot12<true>(reinterpret_cast<const ulonglong2*>(bufB) + r * 64, sw,
                    ks, 0, WMVg, WMVc, WFVu, 128, rstd2, acc);
        cp_wait<0>(); sg_sync(sid);                        // v1 ready
        dot12<true>(reinterpret_cast<const ulonglong2*>(bufA) + r * 64, sw,
                    ks, 64, WMVg, WMVc, WFVu, 128, rstd2, acc);
        {
            float4* rA = red4 + wtid * 3;
            rA[0] = make_float4(hsum(acc[0]), hsum(acc[1]), hsum(acc[2]), hsum(acc[3]));
            rA[1] = make_float4(hsum(acc[4]), hsum(acc[5]), hsum(acc[6]), hsum(acc[7]));
            rA[2] = make_float4(hsum(acc[8]), hsum(acc[9]), hsum(acc[10]), hsum(acc[11]));
        }
        sg_sync(sid);
        // distributed epilogue: 64 threads = 8 rows x 8 items (4 z + 4 tau)
        {
            float mr = st_mr[r];
            if (ec < 4) {               // z for column ecol
                float G = 0.f, Cv = 0.f;
#pragma unroll
                for (int k = 0; k < 8; ++k) {
                    const float* p = (const float*)(red4 + (k * 8 + r) * 3);
                    G  += p[ecol];
                    Cv += p[4 + ecol];
                }
                float gv = G  + sm[OFF_B + ecol];
                float cv = Cv + sm[OFF_B + 4 + ecol];
                if (t > 0) {
                    gv += sm[OFF_B + 28 + ecol]     - mr * sm[OFF_B + 36 + ecol];
                    cv += sm[OFF_B + 28 + 4 + ecol] - mr * sm[OFF_B + 36 + 4 + ecol];
                }
                float sg = 1.f / (1.f + expf(-gv));
                g_z[gR * Hh + cbase + ecol] = sg * tanhf(cv);
            } else {                    // tau for column ecol
                float T = 0.f;
#pragma unroll
                for (int k = 0; k < 8; ++k) {
                    const float* p = (const float*)(red4 + (k * 8 + r) * 3);
                    T += p[8 + ecol];
                }
                float tl = T + sm[OFF_B + 8 + ecol];
                if (t > 0)
                    tl += sm[OFF_B + 44 + ecol] - mr * sm[OFF_B + 48 + ecol];
                float spv = (tl > 20.f) ? tl : log1pf(expf(tl));
                st_dtT[r * 4 + ecol] = DTc / (spv + 1e-6f);
            }
        }
        bar_t += 8;
        bar_arrive(sid, wtid);
        bar_wait(sid, bar_t, wtid);
        if (bid == 0 && wtid < 16) {    // zero LN accs parity par^1 (own rows)
            if (wtid < 8) g_rs[(par ^ 1) * 64 + sid * 8 + wtid] = 0.f;
            else          g_rq[(par ^ 1) * 64 + sid * 8 + (wtid - 8)] = 0.f;
        }

        // ============ PHASE C: a1 = silu(z@Wf1 + bf1) ======================
        stage8(bufA, zbase,        Hh * 4, kk);
        stage8(bufB, zbase + 1024, Hh * 4, kk);
        unsigned long long af[4][2] = {};
        cp_wait<1>(); sg_sync(sid);                        // z0 ready
        dot4(reinterpret_cast<const ulonglong2*>(bufA) + r * 64, sw, ks, 0,
             WF1u, af);
        cp_wait<0>(); sg_sync(sid);                        // z1 ready
        dot4(reinterpret_cast<const ulonglong2*>(bufB) + r * 64, sw, ks, 64,
             WF1u, af);
        red4[wtid] = make_float4(hsum(af[0][0]) + hsum(af[0][1]),
                                 hsum(af[1][0]) + hsum(af[1][1]),
                                 hsum(af[2][0]) + hsum(af[2][1]),
                                 hsum(af[3][0]) + hsum(af[3][1]));
        sg_sync(sid);
        if (ec < 4) {                   // 32 threads: a1[r, ecol]
            float F = 0.f;
#pragma unroll
            for (int k = 0; k < 8; ++k)
                F += ((const float*)(red4 + (k * 8 + r)))[ecol];
            float f1 = F + sm[OFF_B + 12 + ecol];
            g_a1[gR * Hh + cbase + ecol] = f1 / (1.f + expf(-f1));
        }
        bar_t += 8;
        bar_arrive(sid, wtid);
        bar_wait(sid, bar_t, wtid);

        // ===== PHASE D: f = a1@Wf2 + bf2; v = h + dt/tau * f ===============
        stage8(bufA, abase,        Hh * 4, kk);
        stage8(bufB, abase + 1024, Hh * 4, kk);
        unsigned long long ao[4][2] = {};
        cp_wait<1>(); sg_sync(sid);                        // a1_0 ready
        dot4(reinterpret_cast<const ulonglong2*>(bufA) + r * 64, sw, ks, 0,
             WF2u, ao);
        sg_sync(sid);
        if (t + 1 < Tt) {                                  // x(t+1) -> A
            stage8(bufA, xbase + (size_t)(t + 1) * DIN * 4,
                   (size_t)Tt * DIN * 4, kk);
            cp_wait<1>();
        } else {
            cp_wait<0>();
        }
        sg_sync(sid);                                      // a1_1 ready
        dot4(reinterpret_cast<const ulonglong2*>(bufB) + r * 64, sw, ks, 64,
             WF2u, ao);
        red4[wtid] = make_float4(hsum(ao[0][0]) + hsum(ao[0][1]),
                                 hsum(ao[1][0]) + hsum(ao[1][1]),
                                 hsum(ao[2][0]) + hsum(ao[2][1]),
                                 hsum(ao[3][0]) + hsum(ao[3][1]));
        sg_sync(sid);
        if (ec < 4) {                   // 32 threads: v[r, ecol]
            float F = 0.f;
#pragma unroll
            for (int k = 0; k < 8; ++k)
                F += ((const float*)(red4 + (k * 8 + r)))[ecol];
            float f = F + sm[OFF_B + 16 + ecol];
            float v = st_h[r * 4 + ecol] + st_dtT[r * 4 + ecol] * f;
            g_v[gR * Hh + cbase + ecol] = v;
            st_v[r * 4 + ecol] = v;
        }
        sg_sync(sid);
        if (wtid < 8) {                 // one atomic pair per (CTA, row)
            float v0 = st_v[wtid * 4 + 0], v1 = st_v[wtid * 4 + 1];
            float v2 = st_v[wtid * 4 + 2], v3 = st_v[wtid * 4 + 3];
            atomicAdd(&g_rs[par * 64 + sid * 8 + wtid], v0 + v1 + v2 + v3);
            atomicAdd(&g_rq[par * 64 + sid * 8 + wtid],
                      v0 * v0 + v1 * v1 + v2 * v2 + v3 * v3);
        }
        bar_arrive(sid, wtid);          // split: wait in next phase A
        bar_t += 8;
    }

    bar_wait(sid, bar_t, wtid);
    // final output row (t = Tt-1), distributed
    if (ec < 4) {
        int pp = (Tt - 1) & 1;
        float s = __ldcg(&g_rs[pp * 64 + gR]);
        float q = __ldcg(&g_rq[pp * 64 + gR]);
        float muv = s * (1.f / 512.f);
        float var = q * (1.f / 512.f) - muv * muv;
        float rstdv = rsqrtf(var + EPSc);
        float hn = (st_v[r * 4 + ecol] - muv) * rstdv
                   * sm[OFF_B + 20 + ecol] + sm[OFF_B + 24 + ecol];
        out[((size_t)gR * Tt + (Tt - 1)) * Hh + cbase + ecol] = hn;
    }
}

extern "C" void kernel_launch(void* const* d_in, const int* in_sizes, int n_in,
                              void* d_out, int out_size) {
    const float* x     = (const float*)d_in[0];
    const float* Wm    = (const float*)d_in[1];
    const float* bm    = (const float*)d_in[2];
    const float* Wf1   = (const float*)d_in[3];
    const float* bf1   = (const float*)d_in[4];
    const float* Wf2   = (const float*)d_in[5];
    const float* bf2   = (const float*)d_in[6];
    const float* Wt    = (const float*)d_in[7];
    const float* bt    = (const float*)d_in[8];
    const float* gamma = (const float*)d_in[9];
    const float* beta  = (const float*)d_in[10];
    float* out = (float*)d_out;

    cudaFuncSetAttribute(ctlnn_main, cudaFuncAttributeMaxDynamicSharedMemorySize,
                         SMEM_FLOATS * sizeof(float));

    ctlnn_reset<<<64, 256>>>();
    ctlnn_main<<<NCTA, NTHR, SMEM_FLOATS * sizeof(float)>>>(
        x, Wm, bm, Wf1, bf1, Wf2, bf2, Wt, bt, gamma, beta, out);
}

// round 15
// speedup vs baseline: 1.0221x; 1.0221x over previous
#include <cuda_runtime.h>
#include <cmath>

// ---------------------------------------------------------------------------
// CTLNN persistent kernel, round 14: EIGHT staggered row-streams.
// 128 CTAs; each owns 4 H-columns. Each CTA splits into 8 streams of 64
// threads (8 batch rows each), cascaded one phase apart; each stream has its
// own stage buffers, distributed grid-barrier set, and bar.sync scope.
// Per stream: thread (r:8, ks:8) computes all 4 CTA columns over 8 granules.
// Epilogues distributed over the 64 threads; per-row recurrence state in
// SMEM. tau folded through the mapper (3 phases/step); LayerNorm folded into
// phase A; cp.async double-buffered staging; FFMA2 inner loops.
// ---------------------------------------------------------------------------

namespace {
constexpr int Tt   = 1024;
constexpr int DIN  = 256;
constexpr int Hh   = 512;
constexpr int NCTA = 128;
constexpr int NTHR = 512;
constexpr int NSTR = 8;             // row-streams per CTA
constexpr int NBAR = 16;
constexpr int BARSTRIDE = 32;
constexpr float DTc  = 0.01f;
constexpr float EPSc = 1e-5f;

// SMEM float offsets
constexpr int OFF_WMX   = 0;        // 8 x 256 (x-rows: 4 gate + 4 core cols)
constexpr int OFF_WMV   = 2048;     // 8 x 512 (h-rows, gamma-folded)
constexpr int OFF_WFX   = 6144;     // 4 x 256 tau x-fold
constexpr int OFF_WFV   = 7168;     // 4 x 512 tau v-fold (gamma-folded)
constexpr int OFF_WF1   = 9216;     // 4 x 512
constexpr int OFF_WF2   = 11264;    // 4 x 512
constexpr int OFF_STAGE = 13312;    // 8 streams x 2 buffers x 512 float4
constexpr int OFF_RED   = 46080;    // 8 streams x 64 x 3 float4 = 6144 floats
constexpr int OFF_B     = 52224;    // 64 consts
constexpr int OFF_ST    = 52288;    // 8 streams x 128 state floats
constexpr int SMEM_FLOATS = 53312;  // ~213.2 KB
// OFF_B: 0 bmg[4] 4 bmc[4] 8 tauC0[4] 12 bf1[4] 16 bf2[4] 20 gam[4] 24 bet[4]
//        28 Bsum[8] (g,core) 36 Gsum[8] 44 BsumT[4] 48 GsumT[4]
// per-stream state (128): 0 rstd[8] 8 mr[8] 16 dtT[32] 48 h[32] 80 v[32]
}

// Cross-CTA state
__device__ unsigned g_barArr[NSTR][NBAR * BARSTRIDE];   // per-stream counters
__device__ float g_rs[128], g_rq[128];                  // [par][globalRow]
__device__ float g_v[64 * Hh];
__device__ float g_z[64 * Hh];
__device__ float g_a1[64 * Hh];

__global__ void ctlnn_reset() {
    int i = blockIdx.x * blockDim.x + threadIdx.x;
    if (i < NSTR * NBAR * BARSTRIDE) (&g_barArr[0][0])[i] = 0u;
    if (i < 128) { g_rs[i] = 0.f; g_rq[i] = 0.f; }
    for (int k = i; k < 64 * Hh; k += gridDim.x * blockDim.x) g_v[k] = 0.f;
}

// ---- helpers --------------------------------------------------------------
__device__ __forceinline__ void cp16(float4* dst, const void* src) {
    unsigned s = (unsigned)__cvta_generic_to_shared(dst);
    asm volatile("cp.async.cg.shared.global [%0], [%1], 16;" :: "r"(s), "l"(src));
}
__device__ __forceinline__ void cp_commit() {
    asm volatile("cp.async.commit_group;" ::: "memory");
}
template <int N>
__device__ __forceinline__ void cp_wait() {
    asm volatile("cp.async.wait_group %0;" :: "n"(N) : "memory");
}
__device__ __forceinline__ void fma2(unsigned long long& d,
                                     unsigned long long a, unsigned long long b) {
    asm volatile("fma.rn.f32x2 %0, %1, %2, %3;" : "=l"(d) : "l"(a), "l"(b), "l"(d));
}
__device__ __forceinline__ unsigned long long mul2(unsigned long long a,
                                                   unsigned long long b) {
    unsigned long long d;
    asm("mul.rn.f32x2 %0, %1, %2;" : "=l"(d) : "l"(a), "l"(b));
    return d;
}
__device__ __forceinline__ float hsum(unsigned long long u) {
    float lo, hi;
    asm("mov.b64 {%0,%1}, %2;" : "=f"(lo), "=f"(hi) : "l"(u));
    return lo + hi;
}
// per-stream sync (named barrier, 64 threads)
__device__ __forceinline__ void sg_sync(int sid) {
    asm volatile("bar.sync %0, 64;" :: "r"(1 + sid) : "memory");
}

// Distributed per-stream grid barrier.
__device__ __forceinline__ void bar_arrive(int s, int wtid) {
    __threadfence();
    sg_sync(s);
    if (wtid == 0)
        atomicAdd(&g_barArr[s][(blockIdx.x & (NBAR - 1)) * BARSTRIDE], 1u);
}
__device__ __forceinline__ void bar_wait(int s, unsigned target8, int wtid) {
    if (wtid < NBAR) {
        unsigned v;
        do {
            asm volatile("ld.global.acquire.gpu.u32 %0, [%1];"
                         : "=r"(v) : "l"(&g_barArr[s][wtid * BARSTRIDE]));
        } while (v < target8);
    }
    sg_sync(s);
}

// Stage one 8-row x 64-granule(16B) chunk: 64 threads, 8 cp16 each.
__device__ __forceinline__ void stage8(float4* __restrict__ dst,
                                       const char* __restrict__ gbase,
                                       size_t rstrideB, int kk) {
#pragma unroll
    for (int rs = 0; rs < 8; ++rs) {
        cp16(dst + rs * 64 + (kk ^ rs),
             gbase + (size_t)rs * rstrideB + kk * 16);
    }
    cp_commit();
}

// 12-output chunk dot: 4 gate + 4 core + 4 tau. ws = weight granule stride.
template <bool SCALE>
__device__ __forceinline__ void dot12(const ulonglong2* __restrict__ sp, int sw,
                                      int ks, int goff,
                                      const ulonglong2* __restrict__ wg,
                                      const ulonglong2* __restrict__ wc,
                                      const ulonglong2* __restrict__ wt,
                                      int ws, unsigned long long sc,
                                      unsigned long long acc[12]) {
#pragma unroll
    for (int j = 0; j < 8; ++j) {
        int l = j * 8 + ks;
        ulonglong2 a = sp[l ^ sw];
        if (SCALE) { a.x = mul2(a.x, sc); a.y = mul2(a.y, sc); }
        int wi = goff + l;
#pragma unroll
        for (int cc = 0; cc < 4; ++cc) {
            ulonglong2 g = wg[cc * ws + wi];
            fma2(acc[cc], a.x, g.x); fma2(acc[cc], a.y, g.y);
            ulonglong2 c = wc[cc * ws + wi];
            fma2(acc[4 + cc], a.x, c.x); fma2(acc[4 + cc], a.y, c.y);
            ulonglong2 t2 = wt[cc * ws + wi];
            fma2(acc[8 + cc], a.x, t2.x); fma2(acc[8 + cc], a.y, t2.y);
        }
    }
}

// Generic 4-col dot (phases C/D), weight col stride 128 granules.
__device__ __forceinline__ void dot4(const ulonglong2* __restrict__ sp, int sw,
                                     int ks, int goff,
                                     const ulonglong2* __restrict__ w,
                                     unsigned long long acc[4][2]) {
#pragma unroll
    for (int j = 0; j < 8; ++j) {
        int l = j * 8 + ks;
        ulonglong2 a = sp[l ^ sw];
        int wi = goff + l;
#pragma unroll
        for (int cc = 0; cc < 4; ++cc) {
            ulonglong2 ww = w[cc * 128 + wi];
            fma2(acc[cc][0], a.x, ww.x);
            fma2(acc[cc][1], a.y, ww.y);
        }
    }
}

__global__ void __launch_bounds__(NTHR, 1)
ctlnn_main(const float* __restrict__ x,
           const float* __restrict__ Wm,  const float* __restrict__ bm,
           const float* __restrict__ Wf1, const float* __restrict__ bf1,
           const float* __restrict__ Wf2, const float* __restrict__ bf2,
           const float* __restrict__ Wt,  const float* __restrict__ bt,
           const float* __restrict__ gamma, const float* __restrict__ beta,
           float* __restrict__ out) {
    extern __shared__ __align__(16) float sm[];
    const int tid = threadIdx.x;
    const int bid = blockIdx.x;
    const int cbase = bid * 4;

    // ---- one-time weight slice load (whole CTA) ----
    for (int idx = tid; idx < 8 * 256; idx += NTHR) {    // Wm x-rows
        int c = idx >> 8, k = idx & 255;
        int srccol = (c < 4) ? (cbase + c) : (512 + cbase + (c - 4));
        sm[OFF_WMX + idx] = Wm[k * 1024 + srccol];
    }
    for (int idx = tid; idx < 8 * 512; idx += NTHR) {    // Wm h-rows * gamma
        int c = idx >> 9, k = idx & 511;
        int srccol = (c < 4) ? (cbase + c) : (512 + cbase + (c - 4));
        sm[OFF_WMV + idx] = Wm[(256 + k) * 1024 + srccol] * gamma[k];
    }
    for (int idx = tid; idx < 4 * 512; idx += NTHR) {
        int c = idx >> 9, k = idx & 511;
        int col = cbase + c;
        sm[OFF_WF1 + idx] = Wf1[k * 512 + col];
        sm[OFF_WF2 + idx] = Wf2[k * 512 + col];
    }
    for (int idx = tid; idx < NSTR * 128; idx += NTHR)   // zero state blocks
        sm[OFF_ST + idx] = 0.f;
    if (tid < 4) {
        int col = cbase + tid;
        sm[OFF_B +  0 + tid] = bm[col];
        sm[OFF_B +  4 + tid] = bm[512 + col];
        sm[OFF_B + 12 + tid] = bf1[col];
        sm[OFF_B + 16 + tid] = bf2[col];
        sm[OFF_B + 20 + tid] = gamma[col];
        sm[OFF_B + 24 + tid] = beta[col];
    }
    {   // Bsum/Gsum for the 8 A-columns (gate 0..3, core 4..7)
        int w = tid >> 5, lane = tid & 31;
        if (w < 8) {
            int srccol = (w < 4) ? (cbase + w) : (512 + cbase + (w - 4));
            float sb = 0.f, sg = 0.f;
            for (int k = lane; k < 512; k += 32) {
                float wv = Wm[(256 + k) * 1024 + srccol];
                sb += beta[k] * wv;
                sg += gamma[k] * wv;
            }
#pragma unroll
            for (int o = 16; o; o >>= 1) {
                sb += __shfl_xor_sync(~0u, sb, o);
                sg += __shfl_xor_sync(~0u, sg, o);
            }
            if (lane == 0) { sm[OFF_B + 28 + w] = sb; sm[OFF_B + 36 + w] = sg; }
        }
    }
    __syncthreads();
    // ---- tau fold: WfX = WmX_core@Wt, WfV = WmV_core@Wt (gamma-folded) ----
    {
        float* WtS = sm + OFF_STAGE;            // 4 x 512 [c][j]
        float* Tm  = sm + OFF_STAGE + 2048;     // 24 x 512 tile
        for (int idx = tid; idx < 4 * 512; idx += NTHR) {
            int c = idx >> 9, j = idx & 511;
            WtS[idx] = Wt[j * 512 + cbase + c];
        }
        __syncthreads();
        for (int tile = 0; tile < 32; ++tile) {
            int k0 = tile * 24;
            for (int idx = tid; idx < 24 * 128; idx += NTHR) {
                int row = idx >> 7, jj = idx & 127;
                reinterpret_cast<float4*>(Tm)[row * 128 + jj] =
                    __ldg(reinterpret_cast<const float4*>(
                        Wm + (size_t)(k0 + row) * 1024 + 512) + jj);
            }
            __syncthreads();
            int row = tid >> 2, c = tid & 3;
            if (row < 24) {
                const float4* tm = reinterpret_cast<const float4*>(Tm) + row * 128;
                const float4* wt4 = reinterpret_cast<const float4*>(WtS) + c * 128;
                float s = 0.f;
                for (int jj = 0; jj < 128; ++jj) {
                    float4 a = tm[jj], b = wt4[jj];
                    s += a.x * b.x + a.y * b.y + a.z * b.z + a.w * b.w;
                }
                int k = k0 + row;
                if (k < 256) sm[OFF_WFX + c * 256 + k] = s;
                else         sm[OFF_WFV + c * 512 + (k - 256)] = s;   // raw
            }
            __syncthreads();
        }
        int w = tid >> 5, lane = tid & 31;
        if (w >= 8 && w < 12) {             // BsumT/GsumT for c = w-8
            int c = w - 8;
            float sb = 0.f, sg = 0.f;
            for (int k = lane; k < 512; k += 32) {
                float raw = sm[OFF_WFV + c * 512 + k];
                sb += beta[k] * raw;
                sg += gamma[k] * raw;
            }
#pragma unroll
            for (int o = 16; o; o >>= 1) {
                sb += __shfl_xor_sync(~0u, sb, o);
                sg += __shfl_xor_sync(~0u, sg, o);
            }
            if (lane == 0) { sm[OFF_B + 44 + c] = sb; sm[OFF_B + 48 + c] = sg; }
        } else if (w >= 12) {               // tau const C0 for c = w-12
            int c = w - 12;
            float s = 0.f;
            for (int j = lane; j < 512; j += 32)
                s += bm[512 + j] * WtS[c * 512 + j];
#pragma unroll
            for (int o = 16; o; o >>= 1)
                s += __shfl_xor_sync(~0u, s, o);
            if (lane == 0) sm[OFF_B + 8 + c] = s + bt[cbase + c];
        }
        __syncthreads();
        for (int idx = tid; idx < 4 * 512; idx += NTHR)   // gamma-fold WFV
            sm[OFF_WFV + idx] *= gamma[idx & 511];
        __syncthreads();
    }

    // ---------------- per-stream state ----------------
    const int sid  = tid >> 6;          // stream 0..7
    const int wtid = tid & 63;
    const int r    = wtid & 7;          // local row
    const int ks   = wtid >> 3;         // K-slot (0..7)
    const int sw   = r;                 // swizzle key
    const int kk   = wtid;              // staging granule (0..63)
    const int gR   = sid * 8 + r;       // global batch row
    const int ec   = ks;                // epilogue item
    const int ecol = ec & 3;            // epilogue column

    float4* bufA = reinterpret_cast<float4*>(sm + OFF_STAGE) + sid * 1024;
    float4* bufB = bufA + 512;
    float4* red4 = reinterpret_cast<float4*>(sm + OFF_RED) + sid * 192;
    float* st      = sm + OFF_ST + sid * 128;
    float* st_rstd = st;          // 8
    float* st_mr   = st + 8;      // 8
    float* st_dtT  = st + 16;     // 32
    float* st_h    = st + 48;     // 32
    float* st_v    = st + 80;     // 32

    const ulonglong2* WMXg = reinterpret_cast<const ulonglong2*>(sm + OFF_WMX);
    const ulonglong2* WMXc = WMXg + 4 * 64;
    const ulonglong2* WFXu = reinterpret_cast<const ulonglong2*>(sm + OFF_WFX);
    const ulonglong2* WMVg = reinterpret_cast<const ulonglong2*>(sm + OFF_WMV);
    const ulonglong2* WMVc = WMVg + 4 * 128;
    const ulonglong2* WFVu = reinterpret_cast<const ulonglong2*>(sm + OFF_WFV);
    const ulonglong2* WF1u = reinterpret_cast<const ulonglong2*>(sm + OFF_WF1);
    const ulonglong2* WF2u = reinterpret_cast<const ulonglong2*>(sm + OFF_WF2);

    const char* xbase = (const char*)(x + (size_t)sid * 8 * Tt * DIN);
    const char* vbase = (const char*)(g_v  + (size_t)sid * 8 * Hh);
    const char* zbase = (const char*)(g_z  + (size_t)sid * 8 * Hh);
    const char* abase = (const char*)(g_a1 + (size_t)sid * 8 * Hh);

    unsigned bar_t = 0;

    // prefetch x(t=0) into bufA
    stage8(bufA, xbase, (size_t)Tt * DIN * 4, kk);

    // ---- cascade start: stream s waits for stream s-1's phase A of t=0 ----
    if (sid > 0) {
        if (wtid < NBAR) {
            unsigned v;
            do {
                asm volatile("ld.global.acquire.gpu.u32 %0, [%1];"
                             : "=r"(v) : "l"(&g_barArr[sid - 1][wtid * BARSTRIDE]));
            } while (v < 8);
        }
        sg_sync(sid);
    }

    for (int t = 0; t < Tt; ++t) {
        const int par = t & 1;

        // ============ PHASE A (12 outputs; LN + tau folded) ================
        unsigned long long acc[12] = {};
        cp_wait<0>(); sg_sync(sid);                        // x(t) ready (bufA)
        dot12<false>(reinterpret_cast<const ulonglong2*>(bufA) + r * 64, sw,
                     ks, 0, WMXg, WMXc, WFXu, 64, 0ull, acc);
        bar_wait(sid, bar_t, wtid);                        // hidden by x-dot
        stage8(bufB, vbase, Hh * 4, kk);                   // v0 -> B
        stage8(bufA, vbase + 1024, Hh * 4, kk);            // v1 -> A
        // finalize step t-1 (distributed: 32 threads (r, ecol))
        if (t > 0 && ec < 4) {
            int pp = (t - 1) & 1;
            float s = __ldcg(&g_rs[pp * 64 + gR]);
            float q = __ldcg(&g_rq[pp * 64 + gR]);
            float muv = s * (1.f / 512.f);
            float var = q * (1.f / 512.f) - muv * muv;
            float rstdv = rsqrtf(var + EPSc);
            float hn = (st_v[r * 4 + ecol] - muv) * rstdv
                       * sm[OFF_B + 20 + ecol] + sm[OFF_B + 24 + ecol];
            out[((size_t)gR * Tt + (t - 1)) * Hh + cbase + ecol] = hn;
            st_h[r * 4 + ecol] = hn;
            if (ecol == 0) { st_rstd[r] = rstdv; st_mr[r] = muv * rstdv; }
        }
        cp_wait<1>(); sg_sync(sid);                        // v0 ready, rstd vis
        unsigned long long rstd2;
        {
            float rv = st_rstd[r];
            asm("mov.b64 %0, {%1, %1};" : "=l"(rstd2) : "f"(rv));
        }
        dot12<true>(reinterpret_cast<const ulonglong2*>(bufB) + r * 64, sw,
                    ks, 0, WMVg, WMVc, WFVu, 128, rstd2, acc);
        cp_wait<0>(); sg_sync(sid);                        // v1 ready
        dot12<true>(reinterpret_cast<const ulonglong2*>(bufA) + r * 64, sw,
                    ks, 64, WMVg, WMVc, WFVu, 128, rstd2, acc);
        {
            float4* rA = red4 + wtid * 3;
            rA[0] = make_float4(hsum(acc[0]), hsum(acc[1]), hsum(acc[2]), hsum(acc[3]));
            rA[1] = make_float4(hsum(acc[4]), hsum(acc[5]), hsum(acc[6]), hsum(acc[7]));
            rA[2] = make_float4(hsum(acc[8]), hsum(acc[9]), hsum(acc[10]), hsum(acc[11]));
        }
        sg_sync(sid);
        // distributed epilogue: 64 threads = 8 rows x 8 items (4 z + 4 tau)
        {
            float mr = st_mr[r];
            if (ec < 4) {               // z for column ecol
                float G = 0.f, Cv = 0.f;
#pragma unroll
                for (int k = 0; k < 8; ++k) {
                    const float* p = (const float*)(red4 + (k * 8 + r) * 3);
                    G  += p[ecol];
                    Cv += p[4 + ecol];
                }
                float gv = G  + sm[OFF_B + ecol];
                float cv = Cv + sm[OFF_B + 4 + ecol];
                if (t > 0) {
                    gv += sm[OFF_B + 28 + ecol]     - mr * sm[OFF_B + 36 + ecol];
                    cv += sm[OFF_B + 28 + 4 + ecol] - mr * sm[OFF_B + 36 + 4 + ecol];
                }
                float sg = 1.f / (1.f + expf(-gv));
                g_z[gR * Hh + cbase + ecol] = sg * tanhf(cv);
            } else {                    // tau for column ecol
                float T = 0.f;
#pragma unroll
                for (int k = 0; k < 8; ++k) {
                    const float* p = (const float*)(red4 + (k * 8 + r) * 3);
                    T += p[8 + ecol];
                }
                float tl = T + sm[OFF_B + 8 + ecol];
                if (t > 0)
                    tl += sm[OFF_B + 44 + ecol] - mr * sm[OFF_B + 48 + ecol];
                float spv = (tl > 20.f) ? tl : log1pf(expf(tl));
                st_dtT[r * 4 + ecol] = DTc / (spv + 1e-6f);
            }
        }
        bar_t += 8;
        bar_arrive(sid, wtid);
        bar_wait(sid, bar_t, wtid);
        if (bid == 0 && wtid < 16) {    // zero LN accs parity par^1 (own rows)
            if (wtid < 8) g_rs[(par ^ 1) * 64 + sid * 8 + wtid] = 0.f;
            else          g_rq[(par ^ 1) * 64 + sid * 8 + (wtid - 8)] = 0.f;
        }

        // ============ PHASE C: a1 = silu(z@Wf1 + bf1) ======================
        stage8(bufA, zbase,        Hh * 4, kk);
        stage8(bufB, zbase + 1024, Hh * 4, kk);
        unsigned long long af[4][2] = {};
        cp_wait<1>(); sg_sync(sid);                        // z0 ready
        dot4(reinterpret_cast<const ulonglong2*>(bufA) + r * 64, sw, ks, 0,
             WF1u, af);
        cp_wait<0>(); sg_sync(sid);                        // z1 ready
        dot4(reinterpret_cast<const ulonglong2*>(bufB) + r * 64, sw, ks, 64,
             WF1u, af);
        red4[wtid] = make_float4(hsum(af[0][0]) + hsum(af[0][1]),
                                 hsum(af[1][0]) + hsum(af[1][1]),
                                 hsum(af[2][0]) + hsum(af[2][1]),
                                 hsum(af[3][0]) + hsum(af[3][1]));
        sg_sync(sid);
        if (ec < 4) {                   // 32 threads: a1[r, ecol]
            float F = 0.f;
#pragma unroll
            for (int k = 0; k < 8; ++k)
                F += ((const float*)(red4 + (k * 8 + r)))[ecol];
            float f1 = F + sm[OFF_B + 12 + ecol];
            g_a1[gR * Hh + cbase + ecol] = f1 / (1.f + expf(-f1));
        }
        bar_t += 8;
        bar_arrive(sid, wtid);
        bar_wait(sid, bar_t, wtid);

        // ===== PHASE D: f = a1@Wf2 + bf2; v = h + dt/tau * f ===============
        stage8(bufA, abase,        Hh * 4, kk);
        stage8(bufB, abase + 1024, Hh * 4, kk);
        unsigned long long ao[4][2] = {};
        cp_wait<1>(); sg_sync(sid);                        // a1_0 ready
        dot4(reinterpret_cast<const ulonglong2*>(bufA) + r * 64, sw, ks, 0,
             WF2u, ao);
        sg_sync(sid);
        if (t + 1 < Tt) {                                  // x(t+1) -> A
            stage8(bufA, xbase + (size_t)(t + 1) * DIN * 4,
                   (size_t)Tt * DIN * 4, kk);
            cp_wait<1>();
        } else {
            cp_wait<0>();
        }
        sg_sync(sid);                                      // a1_1 ready
        dot4(reinterpret_cast<const ulonglong2*>(bufB) + r * 64, sw, ks, 64,
             WF2u, ao);
        red4[wtid] = make_float4(hsum(ao[0][0]) + hsum(ao[0][1]),
                                 hsum(ao[1][0]) + hsum(ao[1][1]),
                                 hsum(ao[2][0]) + hsum(ao[2][1]),
                                 hsum(ao[3][0]) + hsum(ao[3][1]));
        sg_sync(sid);
        if (ec < 4) {                   // 32 threads: v[r, ecol]
            float F = 0.f;
#pragma unroll
            for (int k = 0; k < 8; ++k)
                F += ((const float*)(red4 + (k * 8 + r)))[ecol];
            float f = F + sm[OFF_B + 16 + ecol];
            float v = st_h[r * 4 + ecol] + st_dtT[r * 4 + ecol] * f;
            g_v[gR * Hh + cbase + ecol] = v;
            st_v[r * 4 + ecol] = v;
        }
        sg_sync(sid);
        if (wtid < 8) {                 // one atomic pair per (CTA, row)
            float v0 = st_v[wtid * 4 + 0], v1 = st_v[wtid * 4 + 1];
            float v2 = st_v[wtid * 4 + 2], v3 = st_v[wtid * 4 + 3];
            atomicAdd(&g_rs[par * 64 + sid * 8 + wtid], v0 + v1 + v2 + v3);
            atomicAdd(&g_rq[par * 64 + sid * 8 + wtid],
                      v0 * v0 + v1 * v1 + v2 * v2 + v3 * v3);
        }
        bar_arrive(sid, wtid);          // split: wait in next phase A
        bar_t += 8;
    }

    bar_wait(sid, bar_t, wtid);
    // final output row (t = Tt-1), distributed
    if (ec < 4) {
        int pp = (Tt - 1) & 1;
        float s = __ldcg(&g_rs[pp * 64 + gR]);
        float q = __ldcg(&g_rq[pp * 64 + gR]);
        float muv = s * (1.f / 512.f);
        float var = q * (1.f / 512.f) - muv * muv;
        float rstdv = rsqrtf(var + EPSc);
        float hn = (st_v[r * 4 + ecol] - muv) * rstdv
                   * sm[OFF_B + 20 + ecol] + sm[OFF_B + 24 + ecol];
        out[((size_t)gR * Tt + (Tt - 1)) * Hh + cbase + ecol] = hn;
    }
}

extern "C" void kernel_launch(void* const* d_in, const int* in_sizes, int n_in,
                              void* d_out, int out_size) {
    const float* x     = (const float*)d_in[0];
    const float* Wm    = (const float*)d_in[1];
    const float* bm    = (const float*)d_in[2];
    const float* Wf1   = (const float*)d_in[3];
    const float* bf1   = (const float*)d_in[4];
    const float* Wf2   = (const float*)d_in[5];
    const float* bf2   = (const float*)d_in[6];
    const float* Wt    = (const float*)d_in[7];
    const float* bt    = (const float*)d_in[8];
    const float* gamma = (const float*)d_in[9];
    const float* beta  = (const float*)d_in[10];
    float* out = (float*)d_out;

    cudaFuncSetAttribute(ctlnn_main, cudaFuncAttributeMaxDynamicSharedMemorySize,
                         SMEM_FLOATS * sizeof(float));

    ctlnn_reset<<<64, 256>>>();
    ctlnn_main<<<NCTA, NTHR, SMEM_FLOATS * sizeof(float)>>>(
        x, Wm, bm, Wf1, bf1, Wf2, bf2, Wt, bt, gamma, beta, out);
}

// round 16
// speedup vs baseline: 1.0468x; 1.0242x over previous
#include <cuda_runtime.h>
#include <cmath>

// ---------------------------------------------------------------------------
// CTLNN persistent kernel, round 14: EIGHT staggered row-streams.
// 128 CTAs; each owns 4 H-columns. Each CTA splits into 8 streams of 64
// threads (8 batch rows each), cascaded one phase apart; each stream has its
// own stage buffers, distributed grid-barrier set, and bar.sync scope.
// Per stream: thread (r:8, ks:8) computes all 4 CTA columns over 8 granules.
// Epilogues distributed over the 64 threads; per-row recurrence state in
// SMEM. tau folded through the mapper (3 phases/step); LayerNorm folded into
// phase A; cp.async double-buffered staging; FFMA2 inner loops.
// ---------------------------------------------------------------------------

namespace {
constexpr int Tt   = 1024;
constexpr int DIN  = 256;
constexpr int Hh   = 512;
constexpr int NCTA = 128;
constexpr int NTHR = 512;
constexpr int NSTR = 8;             // row-streams per CTA
constexpr int NBAR = 16;
constexpr int BARSTRIDE = 32;
constexpr float DTc  = 0.01f;
constexpr float EPSc = 1e-5f;

// SMEM float offsets
constexpr int OFF_WMX   = 0;        // 8 x 256 (x-rows: 4 gate + 4 core cols)
constexpr int OFF_WMV   = 2048;     // 8 x 512 (h-rows, gamma-folded)
constexpr int OFF_WFX   = 6144;     // 4 x 256 tau x-fold
constexpr int OFF_WFV   = 7168;     // 4 x 512 tau v-fold (gamma-folded)
constexpr int OFF_WF1   = 9216;     // 4 x 512
constexpr int OFF_WF2   = 11264;    // 4 x 512
constexpr int OFF_STAGE = 13312;    // 8 streams x 2 buffers x 512 float4
constexpr int OFF_RED   = 46080;    // 8 streams x 64 x 3 float4 = 6144 floats
constexpr int OFF_B     = 52224;    // 64 consts
constexpr int OFF_ST    = 52288;    // 8 streams x 128 state floats
constexpr int SMEM_FLOATS = 53312;  // ~213.2 KB
// OFF_B: 0 bmg[4] 4 bmc[4] 8 tauC0[4] 12 bf1[4] 16 bf2[4] 20 gam[4] 24 bet[4]
//        28 Bsum[8] (g,core) 36 Gsum[8] 44 BsumT[4] 48 GsumT[4]
// per-stream state (128): 0 rstd[8] 8 mr[8] 16 dtT[32] 48 h[32] 80 v[32]
}

// Cross-CTA state
__device__ unsigned g_barArr[NSTR][NBAR * BARSTRIDE];   // per-stream counters
__device__ float g_rs[128], g_rq[128];                  // [par][globalRow]
__device__ float g_v[64 * Hh];
__device__ float g_z[64 * Hh];
__device__ float g_a1[64 * Hh];

__global__ void ctlnn_reset() {
    int i = blockIdx.x * blockDim.x + threadIdx.x;
    if (i < NSTR * NBAR * BARSTRIDE) (&g_barArr[0][0])[i] = 0u;
    if (i < 128) { g_rs[i] = 0.f; g_rq[i] = 0.f; }
    for (int k = i; k < 64 * Hh; k += gridDim.x * blockDim.x) g_v[k] = 0.f;
}

// ---- helpers --------------------------------------------------------------
__device__ __forceinline__ void cp16(float4* dst, const void* src) {
    unsigned s = (unsigned)__cvta_generic_to_shared(dst);
    asm volatile("cp.async.cg.shared.global [%0], [%1], 16;" :: "r"(s), "l"(src));
}
__device__ __forceinline__ void cp_commit() {
    asm volatile("cp.async.commit_group;" ::: "memory");
}
template <int N>
__device__ __forceinline__ void cp_wait() {
    asm volatile("cp.async.wait_group %0;" :: "n"(N) : "memory");
}
__device__ __forceinline__ void fma2(unsigned long long& d,
                                     unsigned long long a, unsigned long long b) {
    asm volatile("fma.rn.f32x2 %0, %1, %2, %3;" : "=l"(d) : "l"(a), "l"(b), "l"(d));
}
__device__ __forceinline__ unsigned long long mul2(unsigned long long a,
                                                   unsigned long long b) {
    unsigned long long d;
    asm("mul.rn.f32x2 %0, %1, %2;" : "=l"(d) : "l"(a), "l"(b));
    return d;
}
__device__ __forceinline__ float hsum(unsigned long long u) {
    float lo, hi;
    asm("mov.b64 {%0,%1}, %2;" : "=f"(lo), "=f"(hi) : "l"(u));
    return lo + hi;
}
// per-stream sync (named barrier, 64 threads)
__device__ __forceinline__ void sg_sync(int sid) {
    asm volatile("bar.sync %0, 64;" :: "r"(1 + sid) : "memory");
}

// Distributed per-stream grid barrier.
__device__ __forceinline__ void bar_arrive(int s, int wtid) {
    __threadfence();
    sg_sync(s);
    if (wtid == 0)
        atomicAdd(&g_barArr[s][(blockIdx.x & (NBAR - 1)) * BARSTRIDE], 1u);
}
__device__ __forceinline__ void bar_wait(int s, unsigned target8, int wtid) {
    if (wtid < NBAR) {
        unsigned v;
        do {
            asm volatile("ld.global.acquire.gpu.u32 %0, [%1];"
                         : "=r"(v) : "l"(&g_barArr[s][wtid * BARSTRIDE]));
        } while (v < target8);
    }
    sg_sync(s);
}

// Stage one 8-row x 64-granule(16B) chunk: 64 threads, 8 cp16 each.
__device__ __forceinline__ void stage8(float4* __restrict__ dst,
                                       const char* __restrict__ gbase,
                                       size_t rstrideB, int kk) {
#pragma unroll
    for (int rs = 0; rs < 8; ++rs) {
        cp16(dst + rs * 64 + (kk ^ rs),
             gbase + (size_t)rs * rstrideB + kk * 16);
    }
    cp_commit();
}

// 12-output chunk dot: 4 gate + 4 core + 4 tau. ws = weight granule stride.
template <bool SCALE>
__device__ __forceinline__ void dot12(const ulonglong2* __restrict__ sp, int sw,
                                      int ks, int goff,
                                      const ulonglong2* __restrict__ wg,
                                      const ulonglong2* __restrict__ wc,
                                      const ulonglong2* __restrict__ wt,
                                      int ws, unsigned long long sc,
                                      unsigned long long acc[12]) {
#pragma unroll
    for (int j = 0; j < 8; ++j) {
        int l = j * 8 + ks;
        ulonglong2 a = sp[l ^ sw];
        if (SCALE) { a.x = mul2(a.x, sc); a.y = mul2(a.y, sc); }
        int wi = goff + l;
#pragma unroll
        for (int cc = 0; cc < 4; ++cc) {
            ulonglong2 g = wg[cc * ws + wi];
            fma2(acc[cc], a.x, g.x); fma2(acc[cc], a.y, g.y);
            ulonglong2 c = wc[cc * ws + wi];
            fma2(acc[4 + cc], a.x, c.x); fma2(acc[4 + cc], a.y, c.y);
            ulonglong2 t2 = wt[cc * ws + wi];
            fma2(acc[8 + cc], a.x, t2.x); fma2(acc[8 + cc], a.y, t2.y);
        }
    }
}

// Generic 4-col dot (phases C/D), weight col stride 128 granules.
__device__ __forceinline__ void dot4(const ulonglong2* __restrict__ sp, int sw,
                                     int ks, int goff,
                                     const ulonglong2* __restrict__ w,
                                     unsigned long long acc[4][2]) {
#pragma unroll
    for (int j = 0; j < 8; ++j) {
        int l = j * 8 + ks;
        ulonglong2 a = sp[l ^ sw];
        int wi = goff + l;
#pragma unroll
        for (int cc = 0; cc < 4; ++cc) {
            ulonglong2 ww = w[cc * 128 + wi];
            fma2(acc[cc][0], a.x, ww.x);
            fma2(acc[cc][1], a.y, ww.y);
        }
    }
}

__global__ void __launch_bounds__(NTHR, 1)
ctlnn_main(const float* __restrict__ x,
           const float* __restrict__ Wm,  const float* __restrict__ bm,
           const float* __restrict__ Wf1, const float* __restrict__ bf1,
           const float* __restrict__ Wf2, const float* __restrict__ bf2,
           const float* __restrict__ Wt,  const float* __restrict__ bt,
           const float* __restrict__ gamma, const float* __restrict__ beta,
           float* __restrict__ out) {
    extern __shared__ __align__(16) float sm[];
    const int tid = threadIdx.x;
    const int bid = blockIdx.x;
    const int cbase = bid * 4;

    // ---- one-time weight slice load (whole CTA) ----
    for (int idx = tid; idx < 8 * 256; idx += NTHR) {    // Wm x-rows
        int c = idx >> 8, k = idx & 255;
        int srccol = (c < 4) ? (cbase + c) : (512 + cbase + (c - 4));
        sm[OFF_WMX + idx] = Wm[k * 1024 + srccol];
    }
    for (int idx = tid; idx < 8 * 512; idx += NTHR) {    // Wm h-rows * gamma
        int c = idx >> 9, k = idx & 511;
        int srccol = (c < 4) ? (cbase + c) : (512 + cbase + (c - 4));
        sm[OFF_WMV + idx] = Wm[(256 + k) * 1024 + srccol] * gamma[k];
    }
    for (int idx = tid; idx < 4 * 512; idx += NTHR) {
        int c = idx >> 9, k = idx & 511;
        int col = cbase + c;
        sm[OFF_WF1 + idx] = Wf1[k * 512 + col];
        sm[OFF_WF2 + idx] = Wf2[k * 512 + col];
    }
    for (int idx = tid; idx < NSTR * 128; idx += NTHR)   // zero state blocks
        sm[OFF_ST + idx] = 0.f;
    if (tid < 4) {
        int col = cbase + tid;
        sm[OFF_B +  0 + tid] = bm[col];
        sm[OFF_B +  4 + tid] = bm[512 + col];
        sm[OFF_B + 12 + tid] = bf1[col];
        sm[OFF_B + 16 + tid] = bf2[col];
        sm[OFF_B + 20 + tid] = gamma[col];
        sm[OFF_B + 24 + tid] = beta[col];
    }
    {   // Bsum/Gsum for the 8 A-columns (gate 0..3, core 4..7)
        int w = tid >> 5, lane = tid & 31;
        if (w < 8) {
            int srccol = (w < 4) ? (cbase + w) : (512 + cbase + (w - 4));
            float sb = 0.f, sg = 0.f;
            for (int k = lane; k < 512; k += 32) {
                float wv = Wm[(256 + k) * 1024 + srccol];
                sb += beta[k] * wv;
                sg += gamma[k] * wv;
            }
#pragma unroll
            for (int o = 16; o; o >>= 1) {
                sb += __shfl_xor_sync(~0u, sb, o);
                sg += __shfl_xor_sync(~0u, sg, o);
            }
            if (lane == 0) { sm[OFF_B + 28 + w] = sb; sm[OFF_B + 36 + w] = sg; }
        }
    }
    __syncthreads();
    // ---- tau fold: WfX = WmX_core@Wt, WfV = WmV_core@Wt (gamma-folded) ----
    {
        float* WtS = sm + OFF_STAGE;            // 4 x 512 [c][j]
        float* Tm  = sm + OFF_STAGE + 2048;     // 24 x 512 tile
        for (int idx = tid; idx < 4 * 512; idx += NTHR) {
            int c = idx >> 9, j = idx & 511;
            WtS[idx] = Wt[j * 512 + cbase + c];
        }
        __syncthreads();
        for (int tile = 0; tile < 32; ++tile) {
            int k0 = tile * 24;
            for (int idx = tid; idx < 24 * 128; idx += NTHR) {
                int row = idx >> 7, jj = idx & 127;
                reinterpret_cast<float4*>(Tm)[row * 128 + jj] =
                    __ldg(reinterpret_cast<const float4*>(
                        Wm + (size_t)(k0 + row) * 1024 + 512) + jj);
            }
            __syncthreads();
            int row = tid >> 2, c = tid & 3;
            if (row < 24) {
                const float4* tm = reinterpret_cast<const float4*>(Tm) + row * 128;
                const float4* wt4 = reinterpret_cast<const float4*>(WtS) + c * 128;
                float s = 0.f;
                for (int jj = 0; jj < 128; ++jj) {
                    float4 a = tm[jj], b = wt4[jj];
                    s += a.x * b.x + a.y * b.y + a.z * b.z + a.w * b.w;
                }
                int k = k0 + row;
                if (k < 256) sm[OFF_WFX + c * 256 + k] = s;
                else         sm[OFF_WFV + c * 512 + (k - 256)] = s;   // raw
            }
            __syncthreads();
        }
        int w = tid >> 5, lane = tid & 31;
        if (w >= 8 && w < 12) {             // BsumT/GsumT for c = w-8
            int c = w - 8;
            float sb = 0.f, sg = 0.f;
            for (int k = lane; k < 512; k += 32) {
                float raw = sm[OFF_WFV + c * 512 + k];
                sb += beta[k] * raw;
                sg += gamma[k] * raw;
            }
#pragma unroll
            for (int o = 16; o; o >>= 1) {
                sb += __shfl_xor_sync(~0u, sb, o);
                sg += __shfl_xor_sync(~0u, sg, o);
            }
            if (lane == 0) { sm[OFF_B + 44 + c] = sb; sm[OFF_B + 48 + c] = sg; }
        } else if (w >= 12) {               // tau const C0 for c = w-12
            int c = w - 12;
            float s = 0.f;
            for (int j = lane; j < 512; j += 32)
                s += bm[512 + j] * WtS[c * 512 + j];
#pragma unroll
            for (int o = 16; o; o >>= 1)
                s += __shfl_xor_sync(~0u, s, o);
            if (lane == 0) sm[OFF_B + 8 + c] = s + bt[cbase + c];
        }
        __syncthreads();
        for (int idx = tid; idx < 4 * 512; idx += NTHR)   // gamma-fold WFV
            sm[OFF_WFV + idx] *= gamma[idx & 511];
        __syncthreads();
    }

    // ---------------- per-stream state ----------------
    const int sid  = tid >> 6;          // stream 0..7
    const int wtid = tid & 63;
    const int r    = wtid & 7;          // local row
    const int ks   = wtid >> 3;         // K-slot (0..7)
    const int sw   = r;                 // swizzle key
    const int kk   = wtid;              // staging granule (0..63)
    const int gR   = sid * 8 + r;       // global batch row
    const int ec   = ks;                // epilogue item
    const int ecol = ec & 3;            // epilogue column

    float4* bufA = reinterpret_cast<float4*>(sm + OFF_STAGE) + sid * 1024;
    float4* bufB = bufA + 512;
    float4* red4 = reinterpret_cast<float4*>(sm + OFF_RED) + sid * 192;
    float* st      = sm + OFF_ST + sid * 128;
    float* st_rstd = st;          // 8
    float* st_mr   = st + 8;      // 8
    float* st_dtT  = st + 16;     // 32
    float* st_h    = st + 48;     // 32
    float* st_v    = st + 80;     // 32

    const ulonglong2* WMXg = reinterpret_cast<const ulonglong2*>(sm + OFF_WMX);
    const ulonglong2* WMXc = WMXg + 4 * 64;
    const ulonglong2* WFXu = reinterpret_cast<const ulonglong2*>(sm + OFF_WFX);
    const ulonglong2* WMVg = reinterpret_cast<const ulonglong2*>(sm + OFF_WMV);
    const ulonglong2* WMVc = WMVg + 4 * 128;
    const ulonglong2* WFVu = reinterpret_cast<const ulonglong2*>(sm + OFF_WFV);
    const ulonglong2* WF1u = reinterpret_cast<const ulonglong2*>(sm + OFF_WF1);
    const ulonglong2* WF2u = reinterpret_cast<const ulonglong2*>(sm + OFF_WF2);

    const char* xbase = (const char*)(x + (size_t)sid * 8 * Tt * DIN);
    const char* vbase = (const char*)(g_v  + (size_t)sid * 8 * Hh);
    const char* zbase = (const char*)(g_z  + (size_t)sid * 8 * Hh);
    const char* abase = (const char*)(g_a1 + (size_t)sid * 8 * Hh);

    unsigned bar_t = 0;

    // prefetch x(t=0) into bufA
    stage8(bufA, xbase, (size_t)Tt * DIN * 4, kk);

    // ---- cascade start: stream s waits for stream s-1's phase A of t=0 ----
    if (sid > 0) {
        if (wtid < NBAR) {
            unsigned v;
            do {
                asm volatile("ld.global.acquire.gpu.u32 %0, [%1];"
                             : "=r"(v) : "l"(&g_barArr[sid - 1][wtid * BARSTRIDE]));
            } while (v < 8);
        }
        sg_sync(sid);
    }

    for (int t = 0; t < Tt; ++t) {
        const int par = t & 1;

        // ============ PHASE A (12 outputs; LN + tau folded) ================
        unsigned long long acc[12] = {};
        cp_wait<0>(); sg_sync(sid);                        // x(t) ready (bufA)
        dot12<false>(reinterpret_cast<const ulonglong2*>(bufA) + r * 64, sw,
                     ks, 0, WMXg, WMXc, WFXu, 64, 0ull, acc);
        bar_wait(sid, bar_t, wtid);                        // hidden by x-dot
        stage8(bufB, vbase, Hh * 4, kk);                   // v0 -> B
        stage8(bufA, vbase + 1024, Hh * 4, kk);            // v1 -> A
        // finalize step t-1 (distributed: 32 threads (r, ecol))
        if (t > 0 && ec < 4) {
            int pp = (t - 1) & 1;
            float s = __ldcg(&g_rs[pp * 64 + gR]);
            float q = __ldcg(&g_rq[pp * 64 + gR]);
            float muv = s * (1.f / 512.f);
            float var = q * (1.f / 512.f) - muv * muv;
            float rstdv = rsqrtf(var + EPSc);
            float hn = (st_v[r * 4 + ecol] - muv) * rstdv
                       * sm[OFF_B + 20 + ecol] + sm[OFF_B + 24 + ecol];
            out[((size_t)gR * Tt + (t - 1)) * Hh + cbase + ecol] = hn;
            st_h[r * 4 + ecol] = hn;
            if (ecol == 0) { st_rstd[r] = rstdv; st_mr[r] = muv * rstdv; }
        }
        cp_wait<1>(); sg_sync(sid);                        // v0 ready, rstd vis
        unsigned long long rstd2;
        {
            float rv = st_rstd[r];
            asm("mov.b64 %0, {%1, %1};" : "=l"(rstd2) : "f"(rv));
        }
        dot12<true>(reinterpret_cast<const ulonglong2*>(bufB) + r * 64, sw,
                    ks, 0, WMVg, WMVc, WFVu, 128, rstd2, acc);
        cp_wait<0>(); sg_sync(sid);                        // v1 ready
        dot12<true>(reinterpret_cast<const ulonglong2*>(bufA) + r * 64, sw,
                    ks, 64, WMVg, WMVc, WFVu, 128, rstd2, acc);
        {
            float4* rA = red4 + wtid * 3;
            rA[0] = make_float4(hsum(acc[0]), hsum(acc[1]), hsum(acc[2]), hsum(acc[3]));
            rA[1] = make_float4(hsum(acc[4]), hsum(acc[5]), hsum(acc[6]), hsum(acc[7]));
            rA[2] = make_float4(hsum(acc[8]), hsum(acc[9]), hsum(acc[10]), hsum(acc[11]));
        }
        sg_sync(sid);
        // distributed epilogue: 64 threads = 8 rows x 8 items (4 z + 4 tau)
        {
            float mr = st_mr[r];
            if (ec < 4) {               // z for column ecol
                float G = 0.f, Cv = 0.f;
#pragma unroll
                for (int k = 0; k < 8; ++k) {
                    const float* p = (const float*)(red4 + (k * 8 + r) * 3);
                    G  += p[ecol];
                    Cv += p[4 + ecol];
                }
                float gv = G  + sm[OFF_B + ecol];
                float cv = Cv + sm[OFF_B + 4 + ecol];
                if (t > 0) {
                    gv += sm[OFF_B + 28 + ecol]     - mr * sm[OFF_B + 36 + ecol];
                    cv += sm[OFF_B + 28 + 4 + ecol] - mr * sm[OFF_B + 36 + 4 + ecol];
                }
                float sg = 1.f / (1.f + expf(-gv));
                g_z[gR * Hh + cbase + ecol] = sg * tanhf(cv);
            } else {                    // tau for column ecol
                float T = 0.f;
#pragma unroll
                for (int k = 0; k < 8; ++k) {
                    const float* p = (const float*)(red4 + (k * 8 + r) * 3);
                    T += p[8 + ecol];
                }
                float tl = T + sm[OFF_B + 8 + ecol];
                if (t > 0)
                    tl += sm[OFF_B + 44 + ecol] - mr * sm[OFF_B + 48 + ecol];
                float spv = (tl > 20.f) ? tl : log1pf(expf(tl));
                st_dtT[r * 4 + ecol] = DTc / (spv + 1e-6f);
            }
        }
        bar_t += 8;
        bar_arrive(sid, wtid);
        bar_wait(sid, bar_t, wtid);
        if (bid == 0 && wtid < 16) {    // zero LN accs parity par^1 (own rows)
            if (wtid < 8) g_rs[(par ^ 1) * 64 + sid * 8 + wtid] = 0.f;
            else          g_rq[(par ^ 1) * 64 + sid * 8 + (wtid - 8)] = 0.f;
        }

        // ============ PHASE C: a1 = silu(z@Wf1 + bf1) ======================
        stage8(bufA, zbase,        Hh * 4, kk);
        stage8(bufB, zbase + 1024, Hh * 4, kk);
        unsigned long long af[4][2] = {};
        cp_wait<1>(); sg_sync(sid);                        // z0 ready
        dot4(reinterpret_cast<const ulonglong2*>(bufA) + r * 64, sw, ks, 0,
             WF1u, af);
        cp_wait<0>(); sg_sync(sid);                        // z1 ready
        dot4(reinterpret_cast<const ulonglong2*>(bufB) + r * 64, sw, ks, 64,
             WF1u, af);
        red4[wtid] = make_float4(hsum(af[0][0]) + hsum(af[0][1]),
                                 hsum(af[1][0]) + hsum(af[1][1]),
                                 hsum(af[2][0]) + hsum(af[2][1]),
                                 hsum(af[3][0]) + hsum(af[3][1]));
        sg_sync(sid);
        if (ec < 4) {                   // 32 threads: a1[r, ecol]
            float F = 0.f;
#pragma unroll
            for (int k = 0; k < 8; ++k)
                F += ((const float*)(red4 + (k * 8 + r)))[ecol];
            float f1 = F + sm[OFF_B + 12 + ecol];
            g_a1[gR * Hh + cbase + ecol] = f1 / (1.f + expf(-f1));
        }
        bar_t += 8;
        bar_arrive(sid, wtid);
        bar_wait(sid, bar_t, wtid);

        // ===== PHASE D: f = a1@Wf2 + bf2; v = h + dt/tau * f ===============
        stage8(bufA, abase,        Hh * 4, kk);
        stage8(bufB, abase + 1024, Hh * 4, kk);
        unsigned long long ao[4][2] = {};
        cp_wait<1>(); sg_sync(sid);                        // a1_0 ready
        dot4(reinterpret_cast<const ulonglong2*>(bufA) + r * 64, sw, ks, 0,
             WF2u, ao);
        sg_sync(sid);
        if (t + 1 < Tt) {                                  // x(t+1) -> A
            stage8(bufA, xbase + (size_t)(t + 1) * DIN * 4,
                   (size_t)Tt * DIN * 4, kk);
            cp_wait<1>();
        } else {
            cp_wait<0>();
        }
        sg_sync(sid);                                      // a1_1 ready
        dot4(reinterpret_cast<const ulonglong2*>(bufB) + r * 64, sw, ks, 64,
             WF2u, ao);
        red4[wtid] = make_float4(hsum(ao[0][0]) + hsum(ao[0][1]),
                                 hsum(ao[1][0]) + hsum(ao[1][1]),
                                 hsum(ao[2][0]) + hsum(ao[2][1]),
                                 hsum(ao[3][0]) + hsum(ao[3][1]));
        sg_sync(sid);
        if (ec < 4) {                   // 32 threads: v[r, ecol]
            float F = 0.f;
#pragma unroll
            for (int k = 0; k < 8; ++k)
                F += ((const float*)(red4 + (k * 8 + r)))[ecol];
            float f = F + sm[OFF_B + 16 + ecol];
            float v = st_h[r * 4 + ecol] + st_dtT[r * 4 + ecol] * f;
            g_v[gR * Hh + cbase + ecol] = v;
            st_v[r * 4 + ecol] = v;
        }
        sg_sync(sid);
        if (wtid < 8) {                 // one atomic pair per (CTA, row)
            float v0 = st_v[wtid * 4 + 0], v1 = st_v[wtid * 4 + 1];
            float v2 = st_v[wtid * 4 + 2], v3 = st_v[wtid * 4 + 3];
            atomicAdd(&g_rs[par * 64 + sid * 8 + wtid], v0 + v1 + v2 + v3);
            atomicAdd(&g_rq[par * 64 + sid * 8 + wtid],
                      v0 * v0 + v1 * v1 + v2 * v2 + v3 * v3);
        }
        bar_arrive(sid, wtid);          // split: wait in next phase A
        bar_t += 8;
    }

    bar_wait(sid, bar_t, wtid);
    // final output row (t = Tt-1), distributed
    if (ec < 4) {
        int pp = (Tt - 1) & 1;
        float s = __ldcg(&g_rs[pp * 64 + gR]);
        float q = __ldcg(&g_rq[pp * 64 + gR]);
        float muv = s * (1.f / 512.f);
        float var = q * (1.f / 512.f) - muv * muv;
        float rstdv = rsqrtf(var + EPSc);
        float hn = (st_v[r * 4 + ecol] - muv) * rstdv
                   * sm[OFF_B + 20 + ecol] + sm[OFF_B + 24 + ecol];
        out[((size_t)gR * Tt + (Tt - 1)) * Hh + cbase + ecol] = hn;
    }
}

extern "C" void kernel_launch(void* const* d_in, const int* in_sizes, int n_in,
                              void* d_out, int out_size) {
    const float* x     = (const float*)d_in[0];
    const float* Wm    = (const float*)d_in[1];
    const float* bm    = (const float*)d_in[2];
    const float* Wf1   = (const float*)d_in[3];
    const float* bf1   = (const float*)d_in[4];
    const float* Wf2   = (const float*)d_in[5];
    const float* bf2   = (const float*)d_in[6];
    const float* Wt    = (const float*)d_in[7];
    const float* bt    = (const float*)d_in[8];
    const float* gamma = (const float*)d_in[9];
    const float* beta  = (const float*)d_in[10];
    float* out = (float*)d_out;

    cudaFuncSetAttribute(ctlnn_main, cudaFuncAttributeMaxDynamicSharedMemorySize,
                         SMEM_FLOATS * sizeof(float));

    ctlnn_reset<<<64, 256>>>();
    ctlnn_main<<<NCTA, NTHR, SMEM_FLOATS * sizeof(float)>>>(
        x, Wm, bm, Wf1, bf1, Wf2, bf2, Wt, bt, gamma, beta, out);
}

// round 17
// speedup vs baseline: 1.1433x; 1.0921x over previous
#include <cuda_runtime.h>
#include <cmath>

// ---------------------------------------------------------------------------
// CTLNN persistent kernel, round 17: FOUR staggered row-streams (R13 config,
// the empirical optimum) + 2-row weight reuse in phases C/D.
// 128 CTAs; each owns 4 H-columns. 4 streams of 128 threads (16 rows each),
// cascaded one phase apart; per-stream stage buffers, distributed grid
// barriers, bar.sync scopes. Phase A: (r:16, ks:8) dot12 (4 g + 4 core +
// 4 tau; tau folded through the mapper). Phases C/D: (rr:8, ks2:16) — each
// thread computes 2 rows with the SAME weight granules, halving weight LDS.
// Epilogues distributed; recurrence state in SMEM; LayerNorm folded into
// phase A; cp.async double-buffered staging; FFMA2 inner loops.
// ---------------------------------------------------------------------------

namespace {
constexpr int Tt   = 1024;
constexpr int DIN  = 256;
constexpr int Hh   = 512;
constexpr int NCTA = 128;
constexpr int NTHR = 512;
constexpr int NBAR = 16;
constexpr int BARSTRIDE = 32;
constexpr float DTc  = 0.01f;
constexpr float EPSc = 1e-5f;

// SMEM float offsets
constexpr int OFF_WMX   = 0;        // 8 x 256 (x-rows: 4 gate + 4 core cols)
constexpr int OFF_WMV   = 2048;     // 8 x 512 (h-rows, gamma-folded)
constexpr int OFF_WFX   = 6144;     // 4 x 256 tau x-fold
constexpr int OFF_WFV   = 7168;     // 4 x 512 tau v-fold (gamma-folded)
constexpr int OFF_WF1   = 9216;     // 4 x 512
constexpr int OFF_WF2   = 11264;    // 4 x 512
constexpr int OFF_STAGE = 13312;    // 4 streams x 2 buffers x 1024 float4
constexpr int OFF_RED   = 46080;    // 4 streams x 384 float4
constexpr int OFF_B     = 52224;    // 64 consts
constexpr int OFF_ST    = 52288;    // 4 streams x 256 state floats
constexpr int SMEM_FLOATS = 53312;  // ~213.2 KB
// OFF_B: 0 bmg[4] 4 bmc[4] 8 tauC0[4] 12 bf1[4] 16 bf2[4] 20 gam[4] 24 bet[4]
//        28 Bsum[8] (g,core) 36 Gsum[8] 44 BsumT[4] 48 GsumT[4]
// per-stream state block (256): 0 rstd[16] 16 mr[16] 32 dtT[64] 96 h[64] 160 v[64]
}

// Cross-CTA state
__device__ unsigned g_barArr[4][NBAR * BARSTRIDE];   // per-stream counters
__device__ float g_rs[128], g_rq[128];               // [par][globalRow]
__device__ float g_v[64 * Hh];
__device__ float g_z[64 * Hh];
__device__ float g_a1[64 * Hh];

__global__ void ctlnn_reset() {
    int i = blockIdx.x * blockDim.x + threadIdx.x;
    if (i < 4 * NBAR * BARSTRIDE) (&g_barArr[0][0])[i] = 0u;
    if (i < 128) { g_rs[i] = 0.f; g_rq[i] = 0.f; }
    for (int k = i; k < 64 * Hh; k += gridDim.x * blockDim.x) g_v[k] = 0.f;
}

// ---- helpers --------------------------------------------------------------
__device__ __forceinline__ void cp16(float4* dst, const void* src) {
    unsigned s = (unsigned)__cvta_generic_to_shared(dst);
    asm volatile("cp.async.cg.shared.global [%0], [%1], 16;" :: "r"(s), "l"(src));
}
__device__ __forceinline__ void cp_commit() {
    asm volatile("cp.async.commit_group;" ::: "memory");
}
template <int N>
__device__ __forceinline__ void cp_wait() {
    asm volatile("cp.async.wait_group %0;" :: "n"(N) : "memory");
}
__device__ __forceinline__ void fma2(unsigned long long& d,
                                     unsigned long long a, unsigned long long b) {
    asm volatile("fma.rn.f32x2 %0, %1, %2, %3;" : "=l"(d) : "l"(a), "l"(b), "l"(d));
}
__device__ __forceinline__ unsigned long long mul2(unsigned long long a,
                                                   unsigned long long b) {
    unsigned long long d;
    asm("mul.rn.f32x2 %0, %1, %2;" : "=l"(d) : "l"(a), "l"(b));
    return d;
}
__device__ __forceinline__ float hsum(unsigned long long u) {
    float lo, hi;
    asm("mov.b64 {%0,%1}, %2;" : "=f"(lo), "=f"(hi) : "l"(u));
    return lo + hi;
}
// per-stream sync (named barrier, 128 threads)
__device__ __forceinline__ void sg_sync(int sid) {
    asm volatile("bar.sync %0, 128;" :: "r"(1 + sid) : "memory");
}

// Distributed per-stream grid barrier.
__device__ __forceinline__ void bar_arrive(int s, int wtid) {
    __threadfence();
    sg_sync(s);
    if (wtid == 0)
        atomicAdd(&g_barArr[s][(blockIdx.x & (NBAR - 1)) * BARSTRIDE], 1u);
}
__device__ __forceinline__ void bar_wait(int s, unsigned target8, int wtid) {
    if (wtid < NBAR) {
        unsigned v;
        do {
            asm volatile("ld.global.acquire.gpu.u32 %0, [%1];"
                         : "=r"(v) : "l"(&g_barArr[s][wtid * BARSTRIDE]));
        } while (v < target8);
    }
    sg_sync(s);
}

// Stage one 16-row x 64-granule(16B) chunk: 128 threads, 8 cp16 each.
__device__ __forceinline__ void stage16(float4* __restrict__ dst,
                                        const char* __restrict__ gbase,
                                        size_t rstrideB, int rp, int kk) {
#pragma unroll
    for (int i = 0; i < 8; ++i) {
        int rs = rp + i * 2;
        cp16(dst + rs * 64 + (kk ^ (rs & 7)),
             gbase + (size_t)rs * rstrideB + kk * 16);
    }
    cp_commit();
}

// 12-output chunk dot: 4 gate + 4 core + 4 tau. ws = weight granule stride.
template <bool SCALE>
__device__ __forceinline__ void dot12(const ulonglong2* __restrict__ sp, int sw,
                                      int ks, int goff,
                                      const ulonglong2* __restrict__ wg,
                                      const ulonglong2* __restrict__ wc,
                                      const ulonglong2* __restrict__ wt,
                                      int ws, unsigned long long sc,
                                      unsigned long long acc[12]) {
#pragma unroll
    for (int j = 0; j < 8; ++j) {
        int l = j * 8 + ks;
        ulonglong2 a = sp[l ^ sw];
        if (SCALE) { a.x = mul2(a.x, sc); a.y = mul2(a.y, sc); }
        int wi = goff + l;
#pragma unroll
        for (int cc = 0; cc < 4; ++cc) {
            ulonglong2 g = wg[cc * ws + wi];
            fma2(acc[cc], a.x, g.x); fma2(acc[cc], a.y, g.y);
            ulonglong2 c = wc[cc * ws + wi];
            fma2(acc[4 + cc], a.x, c.x); fma2(acc[4 + cc], a.y, c.y);
            ulonglong2 t2 = wt[cc * ws + wi];
            fma2(acc[8 + cc], a.x, t2.x); fma2(acc[8 + cc], a.y, t2.y);
        }
    }
}

// 2-row 4-col dot (phases C/D): thread covers rows rr and rr+8 with the SAME
// weight granules (both rows share swizzle key rr). Granules l = j*16 + ks2.
__device__ __forceinline__ void dot4_2r(const ulonglong2* __restrict__ b,
                                        int rr, int ks2, int goff,
                                        const ulonglong2* __restrict__ w,
                                        unsigned long long acc0[4],
                                        unsigned long long acc1[4]) {
    const ulonglong2* sp0 = b + rr * 64;
    const ulonglong2* sp1 = b + (rr + 8) * 64;
#pragma unroll
    for (int j = 0; j < 4; ++j) {
        int l = j * 16 + ks2;
        ulonglong2 a0 = sp0[l ^ rr];
        ulonglong2 a1 = sp1[l ^ rr];
        int wi = goff + l;
#pragma unroll
        for (int cc = 0; cc < 4; ++cc) {
            ulonglong2 ww = w[cc * 128 + wi];
            fma2(acc0[cc], a0.x, ww.x); fma2(acc0[cc], a0.y, ww.y);
            fma2(acc1[cc], a1.x, ww.x); fma2(acc1[cc], a1.y, ww.y);
        }
    }
}

__global__ void __launch_bounds__(NTHR, 1)
ctlnn_main(const float* __restrict__ x,
           const float* __restrict__ Wm,  const float* __restrict__ bm,
           const float* __restrict__ Wf1, const float* __restrict__ bf1,
           const float* __restrict__ Wf2, const float* __restrict__ bf2,
           const float* __restrict__ Wt,  const float* __restrict__ bt,
           const float* __restrict__ gamma, const float* __restrict__ beta,
           float* __restrict__ out) {
    extern __shared__ __align__(16) float sm[];
    const int tid = threadIdx.x;
    const int bid = blockIdx.x;
    const int cbase = bid * 4;

    // ---- one-time weight slice load (whole CTA) ----
    for (int idx = tid; idx < 8 * 256; idx += NTHR) {    // Wm x-rows
        int c = idx >> 8, k = idx & 255;
        int srccol = (c < 4) ? (cbase + c) : (512 + cbase + (c - 4));
        sm[OFF_WMX + idx] = Wm[k * 1024 + srccol];
    }
    for (int idx = tid; idx < 8 * 512; idx += NTHR) {    // Wm h-rows * gamma
        int c = idx >> 9, k = idx & 511;
        int srccol = (c < 4) ? (cbase + c) : (512 + cbase + (c - 4));
        sm[OFF_WMV + idx] = Wm[(256 + k) * 1024 + srccol] * gamma[k];
    }
    for (int idx = tid; idx < 4 * 512; idx += NTHR) {
        int c = idx >> 9, k = idx & 511;
        int col = cbase + c;
        sm[OFF_WF1 + idx] = Wf1[k * 512 + col];
        sm[OFF_WF2 + idx] = Wf2[k * 512 + col];
    }
    for (int idx = tid; idx < 4 * 256; idx += NTHR)      // zero state blocks
        sm[OFF_ST + idx] = 0.f;
    if (tid < 4) {
        int col = cbase + tid;
        sm[OFF_B +  0 + tid] = bm[col];
        sm[OFF_B +  4 + tid] = bm[512 + col];
        sm[OFF_B + 12 + tid] = bf1[col];
        sm[OFF_B + 16 + tid] = bf2[col];
        sm[OFF_B + 20 + tid] = gamma[col];
        sm[OFF_B + 24 + tid] = beta[col];
    }
    {   // Bsum/Gsum for the 8 A-columns (gate 0..3, core 4..7)
        int w = tid >> 5, lane = tid & 31;
        if (w < 8) {
            int srccol = (w < 4) ? (cbase + w) : (512 + cbase + (w - 4));
            float sb = 0.f, sg = 0.f;
            for (int k = lane; k < 512; k += 32) {
                float wv = Wm[(256 + k) * 1024 + srccol];
                sb += beta[k] * wv;
                sg += gamma[k] * wv;
            }
#pragma unroll
            for (int o = 16; o; o >>= 1) {
                sb += __shfl_xor_sync(~0u, sb, o);
                sg += __shfl_xor_sync(~0u, sg, o);
            }
            if (lane == 0) { sm[OFF_B + 28 + w] = sb; sm[OFF_B + 36 + w] = sg; }
        }
    }
    __syncthreads();
    // ---- tau fold: WfX = WmX_core@Wt, WfV = WmV_core@Wt (gamma-folded) ----
    {
        float* WtS = sm + OFF_STAGE;            // 4 x 512 [c][j]
        float* Tm  = sm + OFF_STAGE + 2048;     // 24 x 512 tile
        for (int idx = tid; idx < 4 * 512; idx += NTHR) {
            int c = idx >> 9, j = idx & 511;
            WtS[idx] = Wt[j * 512 + cbase + c];
        }
        __syncthreads();
        for (int tile = 0; tile < 32; ++tile) {
            int k0 = tile * 24;
            for (int idx = tid; idx < 24 * 128; idx += NTHR) {
                int row = idx >> 7, jj = idx & 127;
                reinterpret_cast<float4*>(Tm)[row * 128 + jj] =
                    __ldg(reinterpret_cast<const float4*>(
                        Wm + (size_t)(k0 + row) * 1024 + 512) + jj);
            }
            __syncthreads();
            int row = tid >> 2, c = tid & 3;
            if (row < 24) {
                const float4* tm = reinterpret_cast<const float4*>(Tm) + row * 128;
                const float4* wt4 = reinterpret_cast<const float4*>(WtS) + c * 128;
                float s = 0.f;
                for (int jj = 0; jj < 128; ++jj) {
                    float4 a = tm[jj], b = wt4[jj];
                    s += a.x * b.x + a.y * b.y + a.z * b.z + a.w * b.w;
                }
                int k = k0 + row;
                if (k < 256) sm[OFF_WFX + c * 256 + k] = s;
                else         sm[OFF_WFV + c * 512 + (k - 256)] = s;   // raw
            }
            __syncthreads();
        }
        int w = tid >> 5, lane = tid & 31;
        if (w >= 8 && w < 12) {             // BsumT/GsumT for c = w-8
            int c = w - 8;
            float sb = 0.f, sg = 0.f;
            for (int k = lane; k < 512; k += 32) {
                float raw = sm[OFF_WFV + c * 512 + k];
                sb += beta[k] * raw;
                sg += gamma[k] * raw;
            }
#pragma unroll
            for (int o = 16; o; o >>= 1) {
                sb += __shfl_xor_sync(~0u, sb, o);
                sg += __shfl_xor_sync(~0u, sg, o);
            }
            if (lane == 0) { sm[OFF_B + 44 + c] = sb; sm[OFF_B + 48 + c] = sg; }
        } else if (w >= 12) {               // tau const C0 for c = w-12
            int c = w - 12;
            float s = 0.f;
            for (int j = lane; j < 512; j += 32)
                s += bm[512 + j] * WtS[c * 512 + j];
#pragma unroll
            for (int o = 16; o; o >>= 1)
                s += __shfl_xor_sync(~0u, s, o);
            if (lane == 0) sm[OFF_B + 8 + c] = s + bt[cbase + c];
        }
        __syncthreads();
        for (int idx = tid; idx < 4 * 512; idx += NTHR)   // gamma-fold WFV
            sm[OFF_WFV + idx] *= gamma[idx & 511];
        __syncthreads();
    }

    // ---------------- per-stream state ----------------
    const int sid  = tid >> 7;          // stream 0..3
    const int wtid = tid & 127;
    const int r    = wtid & 15;         // local row (phase A / epilogue)
    const int ks   = wtid >> 4;         // K-slot (phase A)
    const int sw   = r & 7;
    const int rp   = wtid >> 6;         // staging row phase (0..1)
    const int kk   = wtid & 63;         // staging granule
    const int gR   = sid * 16 + r;      // global batch row
    const int ec   = wtid >> 4;         // epilogue item (= ks)
    const int ecol = ec & 3;            // epilogue column
    const int rr   = wtid & 7;          // phases C/D: row pair base
    const int ks2  = wtid >> 3;         // phases C/D: K-slot (0..15)

    float4* bufA = reinterpret_cast<float4*>(sm + OFF_STAGE) + sid * 2048;
    float4* bufB = bufA + 1024;
    float4* red4 = reinterpret_cast<float4*>(sm + OFF_RED) + sid * 384;
    float* st      = sm + OFF_ST + sid * 256;
    float* st_rstd = st;          // 16
    float* st_mr   = st + 16;     // 16
    float* st_dtT  = st + 32;     // 64
    float* st_h    = st + 96;     // 64
    float* st_v    = st + 160;    // 64

    const ulonglong2* WMXg = reinterpret_cast<const ulonglong2*>(sm + OFF_WMX);
    const ulonglong2* WMXc = WMXg + 4 * 64;
    const ulonglong2* WFXu = reinterpret_cast<const ulonglong2*>(sm + OFF_WFX);
    const ulonglong2* WMVg = reinterpret_cast<const ulonglong2*>(sm + OFF_WMV);
    const ulonglong2* WMVc = WMVg + 4 * 128;
    const ulonglong2* WFVu = reinterpret_cast<const ulonglong2*>(sm + OFF_WFV);
    const ulonglong2* WF1u = reinterpret_cast<const ulonglong2*>(sm + OFF_WF1);
    const ulonglong2* WF2u = reinterpret_cast<const ulonglong2*>(sm + OFF_WF2);

    const char* xbase = (const char*)(x + (size_t)sid * 16 * Tt * DIN);
    const char* vbase = (const char*)(g_v  + (size_t)sid * 16 * Hh);
    const char* zbase = (const char*)(g_z  + (size_t)sid * 16 * Hh);
    const char* abase = (const char*)(g_a1 + (size_t)sid * 16 * Hh);

    unsigned bar_t = 0;

    // prefetch x(t=0) into bufA
    stage16(bufA, xbase, (size_t)Tt * DIN * 4, rp, kk);

    // ---- cascade start: stream s waits for stream s-1's phase A of t=0 ----
    if (sid > 0) {
        if (wtid < NBAR) {
            unsigned v;
            do {
                asm volatile("ld.global.acquire.gpu.u32 %0, [%1];"
                             : "=r"(v) : "l"(&g_barArr[sid - 1][wtid * BARSTRIDE]));
            } while (v < 8);
        }
        sg_sync(sid);
    }

    for (int t = 0; t < Tt; ++t) {
        const int par = t & 1;

        // ============ PHASE A (12 outputs; LN + tau folded) ================
        unsigned long long acc[12] = {};
        cp_wait<0>(); sg_sync(sid);                        // x(t) ready (bufA)
        dot12<false>(reinterpret_cast<const ulonglong2*>(bufA) + r * 64, sw,
                     ks, 0, WMXg, WMXc, WFXu, 64, 0ull, acc);
        bar_wait(sid, bar_t, wtid);                        // hidden by x-dot
        stage16(bufB, vbase, Hh * 4, rp, kk);              // v0 -> B
        stage16(bufA, vbase + 1024, Hh * 4, rp, kk);       // v1 -> A
        // finalize step t-1 (distributed: 64 threads, (r, ecol))
        if (t > 0) {
            if (ec < 4) {
                int pp = (t - 1) & 1;
                float s = __ldcg(&g_rs[pp * 64 + gR]);
                float q = __ldcg(&g_rq[pp * 64 + gR]);
                float muv = s * (1.f / 512.f);
                float var = q * (1.f / 512.f) - muv * muv;
                float rstdv = rsqrtf(var + EPSc);
                float hn = (st_v[r * 4 + ecol] - muv) * rstdv
                           * sm[OFF_B + 20 + ecol] + sm[OFF_B + 24 + ecol];
                out[((size_t)gR * Tt + (t - 1)) * Hh + cbase + ecol] = hn;
                st_h[r * 4 + ecol] = hn;
                if (ecol == 0) { st_rstd[r] = rstdv; st_mr[r] = muv * rstdv; }
            }
        }
        cp_wait<1>(); sg_sync(sid);                        // v0 ready, rstd vis
        unsigned long long rstd2;
        {
            float rv = st_rstd[r];
            asm("mov.b64 %0, {%1, %1};" : "=l"(rstd2) : "f"(rv));
        }
        dot12<true>(reinterpret_cast<const ulonglong2*>(bufB) + r * 64, sw,
                    ks, 0, WMVg, WMVc, WFVu, 128, rstd2, acc);
        cp_wait<0>(); sg_sync(sid);                        // v1 ready
        dot12<true>(reinterpret_cast<const ulonglong2*>(bufA) + r * 64, sw,
                    ks, 64, WMVg, WMVc, WFVu, 128, rstd2, acc);
        {
            float4* rA = red4 + wtid * 3;
            rA[0] = make_float4(hsum(acc[0]), hsum(acc[1]), hsum(acc[2]), hsum(acc[3]));
            rA[1] = make_float4(hsum(acc[4]), hsum(acc[5]), hsum(acc[6]), hsum(acc[7]));
            rA[2] = make_float4(hsum(acc[8]), hsum(acc[9]), hsum(acc[10]), hsum(acc[11]));
        }
        sg_sync(sid);
        // distributed epilogue: 128 threads = 16 rows x 8 items (4 z + 4 tau)
        {
            float mr = st_mr[r];
            if (ec < 4) {               // z for column ecol
                float G = 0.f, Cv = 0.f;
#pragma unroll
                for (int k = 0; k < 8; ++k) {
                    const float* p = (const float*)(red4 + (r + 16 * k) * 3);
                    G  += p[ecol];
                    Cv += p[4 + ecol];
                }
                float gv = G  + sm[OFF_B + ecol];
                float cv = Cv + sm[OFF_B + 4 + ecol];
                if (t > 0) {
                    gv += sm[OFF_B + 28 + ecol]     - mr * sm[OFF_B + 36 + ecol];
                    cv += sm[OFF_B + 28 + 4 + ecol] - mr * sm[OFF_B + 36 + 4 + ecol];
                }
                float sg = 1.f / (1.f + expf(-gv));
                g_z[gR * Hh + cbase + ecol] = sg * tanhf(cv);
            } else {                    // tau for column ecol
                float T = 0.f;
#pragma unroll
                for (int k = 0; k < 8; ++k) {
                    const float* p = (const float*)(red4 + (r + 16 * k) * 3);
                    T += p[8 + ecol];
                }
                float tl = T + sm[OFF_B + 8 + ecol];
                if (t > 0)
                    tl += sm[OFF_B + 44 + ecol] - mr * sm[OFF_B + 48 + ecol];
                float spv = (tl > 20.f) ? tl : log1pf(expf(tl));
                st_dtT[r * 4 + ecol] = DTc / (spv + 1e-6f);
            }
        }
        bar_t += 8;
        bar_arrive(sid, wtid);
        bar_wait(sid, bar_t, wtid);
        if (bid == 0 && wtid < 32) {    // zero LN accs parity par^1 (own rows)
            if (wtid < 16) g_rs[(par ^ 1) * 64 + sid * 16 + wtid] = 0.f;
            else           g_rq[(par ^ 1) * 64 + sid * 16 + (wtid - 16)] = 0.f;
        }

        // ============ PHASE C: a1 = silu(z@Wf1 + bf1), 2-row weight reuse ==
        stage16(bufA, zbase,        Hh * 4, rp, kk);
        stage16(bufB, zbase + 1024, Hh * 4, rp, kk);
        unsigned long long af0[4] = {}, af1[4] = {};
        cp_wait<1>(); sg_sync(sid);                        // z0 ready
        dot4_2r(reinterpret_cast<const ulonglong2*>(bufA), rr, ks2, 0,
                WF1u, af0, af1);
        cp_wait<0>(); sg_sync(sid);                        // z1 ready
        dot4_2r(reinterpret_cast<const ulonglong2*>(bufB), rr, ks2, 64,
                WF1u, af0, af1);
        red4[wtid]       = make_float4(hsum(af0[0]), hsum(af0[1]),
                                       hsum(af0[2]), hsum(af0[3]));
        red4[128 + wtid] = make_float4(hsum(af1[0]), hsum(af1[1]),
                                       hsum(af1[2]), hsum(af1[3]));
        sg_sync(sid);
        if (ec < 4) {                   // 64 threads: a1[r, ecol], 16 partials
            int rbase = (r & 7) + ((r >> 3) << 7);
            float F = 0.f;
#pragma unroll
            for (int k = 0; k < 16; ++k)
                F += ((const float*)(red4 + rbase + k * 8))[ecol];
            float f1 = F + sm[OFF_B + 12 + ecol];
            g_a1[gR * Hh + cbase + ecol] = f1 / (1.f + expf(-f1));
        }
        bar_t += 8;
        bar_arrive(sid, wtid);
        bar_wait(sid, bar_t, wtid);

        // ===== PHASE D: f = a1@Wf2 + bf2; v = h + dt/tau*f; 2-row reuse ====
        stage16(bufA, abase,        Hh * 4, rp, kk);
        stage16(bufB, abase + 1024, Hh * 4, rp, kk);
        unsigned long long ao0[4] = {}, ao1[4] = {};
        cp_wait<1>(); sg_sync(sid);                        // a1_0 ready
        dot4_2r(reinterpret_cast<const ulonglong2*>(bufA), rr, ks2, 0,
                WF2u, ao0, ao1);
        sg_sync(sid);
        if (t + 1 < Tt) {                                  // x(t+1) -> A
            stage16(bufA, xbase + (size_t)(t + 1) * DIN * 4,
                    (size_t)Tt * DIN * 4, rp, kk);
            cp_wait<1>();
        } else {
            cp_wait<0>();
        }
        sg_sync(sid);                                      // a1_1 ready
        dot4_2r(reinterpret_cast<const ulonglong2*>(bufB), rr, ks2, 64,
                WF2u, ao0, ao1);
        red4[wtid]       = make_float4(hsum(ao0[0]), hsum(ao0[1]),
                                       hsum(ao0[2]), hsum(ao0[3]));
        red4[128 + wtid] = make_float4(hsum(ao1[0]), hsum(ao1[1]),
                                       hsum(ao1[2]), hsum(ao1[3]));
        sg_sync(sid);
        if (ec < 4) {                   // 64 threads: v[r, ecol], 16 partials
            int rbase = (r & 7) + ((r >> 3) << 7);
            float F = 0.f;
#pragma unroll
            for (int k = 0; k < 16; ++k)
                F += ((const float*)(red4 + rbase + k * 8))[ecol];
            float f = F + sm[OFF_B + 16 + ecol];
            float v = st_h[r * 4 + ecol] + st_dtT[r * 4 + ecol] * f;
            g_v[gR * Hh + cbase + ecol] = v;
            st_v[r * 4 + ecol] = v;
        }
        sg_sync(sid);
        if (wtid < 16) {                // one atomic pair per (CTA, row)
            float s0 = st_v[wtid * 4 + 0] + st_v[wtid * 4 + 1]
                     + st_v[wtid * 4 + 2] + st_v[wtid * 4 + 3];
            float q0 = st_v[wtid * 4 + 0] * st_v[wtid * 4 + 0]
                     + st_v[wtid * 4 + 1] * st_v[wtid * 4 + 1]
                     + st_v[wtid * 4 + 2] * st_v[wtid * 4 + 2]
                     + st_v[wtid * 4 + 3] * st_v[wtid * 4 + 3];
            atomicAdd(&g_rs[par * 64 + sid * 16 + wtid], s0);
            atomicAdd(&g_rq[par * 64 + sid * 16 + wtid], q0);
        }
        bar_arrive(sid, wtid);          // split: wait in next phase A
        bar_t += 8;
    }

    bar_wait(sid, bar_t, wtid);
    // final output row (t = Tt-1), distributed
    if (ec < 4) {
        int pp = (Tt - 1) & 1;
        float s = __ldcg(&g_rs[pp * 64 + gR]);
        float q = __ldcg(&g_rq[pp * 64 + gR]);
        float muv = s * (1.f / 512.f);
        float var = q * (1.f / 512.f) - muv * muv;
        float rstdv = rsqrtf(var + EPSc);
        float hn = (st_v[r * 4 + ecol] - muv) * rstdv
                   * sm[OFF_B + 20 + ecol] + sm[OFF_B + 24 + ecol];
        out[((size_t)gR * Tt + (Tt - 1)) * Hh + cbase + ecol] = hn;
    }
}

extern "C" void kernel_launch(void* const* d_in, const int* in_sizes, int n_in,
                              void* d_out, int out_size) {
    const float* x     = (const float*)d_in[0];
    const float* Wm    = (const float*)d_in[1];
    const float* bm    = (const float*)d_in[2];
    const float* Wf1   = (const float*)d_in[3];
    const float* bf1   = (const float*)d_in[4];
    const float* Wf2   = (const float*)d_in[5];
    const float* bf2   = (const float*)d_in[6];
    const float* Wt    = (const float*)d_in[7];
    const float* bt    = (const float*)d_in[8];
    const float* gamma = (const float*)d_in[9];
    const float* beta  = (const float*)d_in[10];
    float* out = (float*)d_out;

    cudaFuncSetAttribute(ctlnn_main, cudaFuncAttributeMaxDynamicSharedMemorySize,
                         SMEM_FLOATS * sizeof(float));

    ctlnn_reset<<<64, 256>>>();
    ctlnn_main<<<NCTA, NTHR, SMEM_FLOATS * sizeof(float)>>>(
        x, Wm, bm, Wf1, bf1, Wf2, bf2, Wt, bt, gamma, beta, out);
}